// round 7
// baseline (speedup 1.0000x reference)
#include <cuda_runtime.h>
#include <cstdint>

#define D_MODEL 2048
#define BB 2
#define SS 2048
#define HH 16
#define DHD 128
#define PAST 2048
#define TOTAL 4096
#define BHH 32
#define M_ROWS 4096
#define QK_SCALE 0.08838834764831845f

// Scratch (allocation-free rule: __device__ globals). All hold tf32 bit patterns.
__device__ uint32_t g_Xt[(size_t)M_ROWS * D_MODEL];
__device__ uint32_t g_Wt[4 * (size_t)D_MODEL * D_MODEL];
__device__ uint32_t g_Qt[(size_t)BHH * SS * DHD];        // (bh,s,dh), pre-scaled
__device__ uint32_t g_Kt[(size_t)BHH * TOTAL * DHD];     // (bh,key,dh)
__device__ uint32_t g_Vt[(size_t)BHH * DHD * TOTAL];     // V transposed (bh,dh,key)
__device__ uint32_t g_At[(size_t)BB * SS * D_MODEL];     // attn (b,s,dm)

// ---------------------------------------------------------------------------
// Helpers
// ---------------------------------------------------------------------------
__device__ __forceinline__ uint32_t to_tf32(float f) {
    uint32_t u;
    asm("cvt.rna.tf32.f32 %0, %1;" : "=r"(u) : "f"(f));
    return u;
}

__device__ __forceinline__ uint4 cvt4(float4 v) {
    uint4 r;
    r.x = to_tf32(v.x); r.y = to_tf32(v.y);
    r.z = to_tf32(v.z); r.w = to_tf32(v.w);
    return r;
}

__device__ __forceinline__ void mma_tf32(float* c,
                                         uint32_t a0, uint32_t a1, uint32_t a2, uint32_t a3,
                                         uint32_t b0, uint32_t b1) {
    asm volatile(
        "mma.sync.aligned.m16n8k8.row.col.f32.tf32.tf32.f32 "
        "{%0,%1,%2,%3}, {%4,%5,%6,%7}, {%8,%9}, {%0,%1,%2,%3};"
        : "+f"(c[0]), "+f"(c[1]), "+f"(c[2]), "+f"(c[3])
        : "r"(a0), "r"(a1), "r"(a2), "r"(a3), "r"(b0), "r"(b1));
}

// Fast exp on the FMA pipe (arg <= 0 always). fexp(0) == 1.0f exactly.
__device__ __forceinline__ float fexp(float x) {
    float t = fmaxf(x * 1.4426950408889634f, -126.0f);
    float r = t + 12582912.0f;
    float fn = r - 12582912.0f;
    float f = t - fn;
    int n = __float_as_int(r) - 0x4B400000;
    float p = 0.0013333558f;
    p = fmaf(p, f, 0.0096181291f);
    p = fmaf(p, f, 0.055504109f);
    p = fmaf(p, f, 0.24022651f);
    p = fmaf(p, f, 0.69314718f);
    p = fmaf(p, f, 1.0f);
    return p * __int_as_float((n + 127) << 23);
}

__device__ __forceinline__ void cpasync16(void* smem_dst, const void* gsrc) {
    uint32_t s = (uint32_t)__cvta_generic_to_shared(smem_dst);
    asm volatile("cp.async.cg.shared.global [%0], [%1], 16;" :: "r"(s), "l"(gsrc));
}
__device__ __forceinline__ void cpasync_commit() {
    asm volatile("cp.async.commit_group;");
}

// ---------------------------------------------------------------------------
// Prep kernels
// ---------------------------------------------------------------------------
__global__ void cvt_x_kernel(const float4* __restrict__ x, uint4* __restrict__ out) {
    int i = blockIdx.x * blockDim.x + threadIdx.x;
    if (i < M_ROWS * D_MODEL / 4) out[i] = cvt4(x[i]);
}

__global__ void cvt_w_kernel(const float4* __restrict__ w0, const float4* __restrict__ w1,
                             const float4* __restrict__ w2, const float4* __restrict__ w3,
                             uint4* __restrict__ out) {
    int z = blockIdx.y;
    const float4* src = (z == 0) ? w0 : (z == 1) ? w1 : (z == 2) ? w2 : w3;
    int i = blockIdx.x * blockDim.x + threadIdx.x;
    const int n4 = D_MODEL * D_MODEL / 4;
    if (i < n4) out[(size_t)z * n4 + i] = cvt4(src[i]);
}

__global__ void copy_past_k_kernel(const float4* __restrict__ pk,
                                   float4* __restrict__ kc, uint4* __restrict__ kt) {
    int i = blockIdx.x * blockDim.x + threadIdx.x;
    if (i >= BHH * PAST * DHD / 4) return;
    int bh  = i >> 16;
    int rem = i & 65535;
    int dst = (bh << 17) + rem;
    float4 v = pk[i];
    kc[dst] = v;
    kt[dst] = cvt4(v);
}

__global__ __launch_bounds__(256) void transpose_past_v_kernel(
    const float* __restrict__ pv, float* __restrict__ vc, uint32_t* __restrict__ vt) {
    __shared__ float ts[32][33];
    int bh = blockIdx.z;
    int k0 = blockIdx.x * 32;
    int d0 = blockIdx.y * 32;
    int tx = threadIdx.x & 31, ty = threadIdx.x >> 5;

    const float* src = pv + ((size_t)bh * PAST + k0) * DHD + d0;
    float* cdst      = vc + ((size_t)bh * TOTAL + k0) * DHD + d0;
#pragma unroll
    for (int j = 0; j < 4; j++) {
        int r = ty + 8 * j;
        float v = src[(size_t)r * DHD + tx];
        cdst[(size_t)r * DHD + tx] = v;
        ts[r][tx] = v;
    }
    __syncthreads();
    uint32_t* tdst = vt + (size_t)bh * DHD * TOTAL;
#pragma unroll
    for (int j = 0; j < 4; j++) {
        int d = d0 + ty + 8 * j;
        tdst[(size_t)d * TOTAL + k0 + tx] = to_tf32(ts[tx][ty + 8 * j]);
    }
}

// ---------------------------------------------------------------------------
// TF32 GEMM, CTA 128x256, warp tile 64x64 (8 warps 2x4), BK=32, 3-stage
// cp.async. tf32-bit inputs. FUSED=1: z selects Wq/Wk/Wv + special epilogues.
// ---------------------------------------------------------------------------
#define GLDW 48
#define GSTAGE ((128 + 256) * GLDW)
#define GEMM_SMEM (3 * GSTAGE * 4)   // 221184 B

template <int FUSED>
__global__ __launch_bounds__(256) void gemm_pipe_kernel(
    const uint32_t* __restrict__ A, const uint32_t* __restrict__ Wt,
    float* __restrict__ C0, float* __restrict__ C1, float* __restrict__ C2,
    uint32_t* __restrict__ Qt, uint32_t* __restrict__ Kt, uint32_t* __restrict__ Vt) {
    extern __shared__ uint32_t smg[];

    int t    = threadIdx.x;
    int warp = t >> 5, lane = t & 31;
    int gid  = lane >> 2, tid4 = lane & 3;
    int wm   = (warp & 1) * 64;
    int wn   = (warp >> 1) * 64;
    int m0   = blockIdx.y * 128;
    int n0   = blockIdx.x * 256;
    int z    = FUSED ? blockIdx.z : 0;

    const uint32_t* Ab = A + (size_t)m0 * D_MODEL;
    const uint32_t* Bb = Wt + (FUSED ? (size_t)z * D_MODEL * D_MODEL : 0) + (size_t)n0 * D_MODEL;

    float acc[4][8][4];
#pragma unroll
    for (int mf = 0; mf < 4; mf++)
#pragma unroll
        for (int nf = 0; nf < 8; nf++)
#pragma unroll
            for (int c = 0; c < 4; c++) acc[mf][nf][c] = 0.0f;

    const int NT = D_MODEL / 32;  // 64

#define GEMM_ISSUE(KT, STG)                                                        \
    {                                                                              \
        uint32_t* As_ = smg + (STG) * GSTAGE;                                      \
        uint32_t* Bs_ = As_ + 128 * GLDW;                                          \
        const uint32_t* ab = Ab + (KT) * 32;                                       \
        const uint32_t* bb = Bb + (KT) * 32;                                       \
        _Pragma("unroll")                                                          \
        for (int j = 0; j < 4; j++) {                                              \
            int g  = t + 256 * j;                                                  \
            int r  = g >> 3;                                                       \
            int c4 = g & 7;                                                        \
            cpasync16(As_ + r * GLDW + c4 * 4, ab + (size_t)r * D_MODEL + c4 * 4); \
        }                                                                          \
        _Pragma("unroll")                                                          \
        for (int j = 0; j < 8; j++) {                                              \
            int g  = t + 256 * j;                                                  \
            int r  = g >> 3;                                                       \
            int c4 = g & 7;                                                        \
            cpasync16(Bs_ + r * GLDW + c4 * 4, bb + (size_t)r * D_MODEL + c4 * 4); \
        }                                                                          \
    }

    GEMM_ISSUE(0, 0); cpasync_commit();
    GEMM_ISSUE(1, 1); cpasync_commit();

    for (int kt = 0; kt < NT; kt++) {
        asm volatile("cp.async.wait_group 1;");
        __syncthreads();
        if (kt + 2 < NT) GEMM_ISSUE(kt + 2, (kt + 2) % 3);
        cpasync_commit();

        const uint32_t* As = smg + (kt % 3) * GSTAGE;
        const uint32_t* Bs = As + 128 * GLDW;
#pragma unroll
        for (int jj = 0; jj < 2; jj++) {
            uint4 bq[8];
#pragma unroll
            for (int nf = 0; nf < 8; nf++)
                bq[nf] = *(const uint4*)&Bs[(wn + 8 * nf + gid) * GLDW + jj * 16 + tid4 * 4];
#pragma unroll
            for (int mf = 0; mf < 4; mf++) {
                uint4 al = *(const uint4*)&As[(wm + 16 * mf + gid) * GLDW + jj * 16 + tid4 * 4];
                uint4 ah = *(const uint4*)&As[(wm + 16 * mf + gid + 8) * GLDW + jj * 16 + tid4 * 4];
#pragma unroll
                for (int nf = 0; nf < 8; nf++) {
                    mma_tf32(acc[mf][nf], al.x, ah.x, al.y, ah.y, bq[nf].x, bq[nf].y);
                    mma_tf32(acc[mf][nf], al.z, ah.z, al.w, ah.w, bq[nf].z, bq[nf].w);
                }
            }
        }
    }
#undef GEMM_ISSUE

    // Epilogue
#pragma unroll
    for (int mf = 0; mf < 4; mf++)
#pragma unroll
        for (int nf = 0; nf < 8; nf++)
#pragma unroll
            for (int h = 0; h < 2; h++) {
                int m = m0 + wm + 16 * mf + gid + 8 * h;
                int n = n0 + wn + 8 * nf + 2 * tid4;
                float2 v;
                v.x = acc[mf][nf][2 * h];
                v.y = acc[mf][nf][2 * h + 1];
                if (!FUSED) {
                    *(float2*)&C0[(size_t)m * D_MODEL + n] = v;
                } else {
                    int bb = m >> 11, ss = m & 2047;
                    int hd = n >> 7,  di = n & 127;
                    int bhh = bb * HH + hd;
                    if (z == 0) {
                        v.x *= QK_SCALE; v.y *= QK_SCALE;
                        uint2 u; u.x = to_tf32(v.x); u.y = to_tf32(v.y);
                        *(uint2*)&Qt[((size_t)bhh * SS + ss) * DHD + di] = u;
                    } else if (z == 1) {
                        size_t idx = ((size_t)bhh * TOTAL + (PAST + ss)) * DHD + di;
                        *(float2*)&C1[idx] = v;
                        uint2 u; u.x = to_tf32(v.x); u.y = to_tf32(v.y);
                        *(uint2*)&Kt[idx] = u;
                    } else {
                        size_t idx = ((size_t)bhh * TOTAL + (PAST + ss)) * DHD + di;
                        *(float2*)&C2[idx] = v;
                        size_t key = PAST + ss;
                        Vt[(size_t)bhh * DHD * TOTAL + (size_t)di * TOTAL + key]       = to_tf32(v.x);
                        Vt[(size_t)bhh * DHD * TOTAL + (size_t)(di + 1) * TOTAL + key] = to_tf32(v.y);
                    }
                }
            }
}

// ---------------------------------------------------------------------------
// Flash attention, tf32 mma. CTA: 256 q-rows x 64 keys/iter, 256 thr, 8 warps.
// Warp w owns 32 q-rows [w*32, w*32+32), all keys, all 128 d.
// Q fragments streamed from global (L2). K: LDG->reg prefetch + STS (single
// buffer). Vt: 2-stage cp.async. P: per-warp smem (pad 88).
// smem: Ks[64][144] + Vts[2][128][80] + Ps[256][88] = 208896 B.
// ---------------------------------------------------------------------------
#define FBM 256
#define KLD 144
#define VTLD 80
#define PLD 88
#define FA_SMEM ((64 * KLD + 2 * 128 * VTLD + 256 * PLD) * 4)

__global__ __launch_bounds__(256) void flash_attn_tc_kernel(
    const uint32_t* __restrict__ Qt, const uint32_t* __restrict__ Ktg,
    const uint32_t* __restrict__ Vtg, uint32_t* __restrict__ Out) {
    extern __shared__ uint32_t sm[];
    uint32_t* Ks  = sm;                      // [64][KLD]
    uint32_t* Vts = sm + 64 * KLD;           // [2][128][VTLD]
    uint32_t* Ps  = Vts + 2 * 128 * VTLD;    // [256][PLD]

    int t    = threadIdx.x;
    int warp = t >> 5, lane = t & 31;
    int gid  = lane >> 2, tid4 = lane & 3;
    int mq   = warp * 32;

    int bh = blockIdx.y;
    int q0 = (gridDim.x - 1 - blockIdx.x) * FBM;  // big tiles launch first

    const uint32_t* Kb = Ktg + (size_t)bh * TOTAL * DHD;
    const uint32_t* Vb = Vtg + (size_t)bh * DHD * TOTAL;
    // Q fragment base: row q0+mq+gid, col 4*tid4 (row-major = fragment layout)
    const uint32_t* Qr = Qt + ((size_t)bh * SS + (q0 + mq + gid)) * DHD + 4 * tid4;

    float m_i[4], l_i[4];
#pragma unroll
    for (int r = 0; r < 4; r++) { m_i[r] = -1e30f; l_i[r] = 0.0f; }
    float po[2][16][4];
#pragma unroll
    for (int rf = 0; rf < 2; rf++)
#pragma unroll
        for (int nf = 0; nf < 16; nf++)
#pragma unroll
            for (int c = 0; c < 4; c++) po[rf][nf][c] = 0.0f;

#define FA_ISSUE_V(KT, STG)                                                            \
    {                                                                                  \
        int k0_ = (KT) * 64;                                                           \
        uint32_t* vsd = Vts + (STG) * 128 * VTLD;                                      \
        _Pragma("unroll")                                                              \
        for (int i = 0; i < 8; i++) {                                                  \
            int id = t + 256 * i;                                                      \
            int d = id >> 4, kg = id & 15;                                             \
            cpasync16(vsd + d * VTLD + kg * 4, Vb + (size_t)d * TOTAL + k0_ + kg * 4); \
        }                                                                              \
    }

#define FA_KPREF(KT)                                                               \
    {                                                                              \
        int k0_ = (KT) * 64;                                                       \
        _Pragma("unroll")                                                          \
        for (int i = 0; i < 8; i++) {                                              \
            int id = t + 256 * i;                                                  \
            int r = id >> 5, c = id & 31;                                          \
            kr[i] = *(const uint4*)&Kb[(size_t)(k0_ + r) * DHD + c * 4];           \
        }                                                                          \
    }

    int nkt = (PAST + q0 + FBM) / 64;

    uint4 kr[8];
    FA_KPREF(0);
    FA_ISSUE_V(0, 0); cpasync_commit();

    for (int kt = 0; kt < nkt; kt++) {
        int k0 = kt * 64;
        int rel = k0 - PAST - q0;

        __syncthreads();  // prior QK reads of Ks + prior PV reads of Vts stage done
        // STS K[kt] (row = warp+8i, full 128-word row per warp-instr, conflict-free)
#pragma unroll
        for (int i = 0; i < 8; i++) {
            int id = t + 256 * i;
            int r = id >> 5, c = id & 31;
            *(uint4*)&Ks[r * KLD + c * 4] = kr[i];
        }
        if (kt + 1 < nkt) {
            FA_ISSUE_V(kt + 1, (kt + 1) & 1);
            cpasync_commit();
            asm volatile("cp.async.wait_group 1;");
        } else {
            asm volatile("cp.async.wait_group 0;");
        }
        __syncthreads();  // Ks + V[kt] visible

        const uint32_t* vsb = Vts + (kt & 1) * 128 * VTLD;

        bool warp_live = (rel <= mq + 31);  // else fully masked for this warp
        if (warp_live) {
            // ---- S = Q K^T : 32 rows x 64 keys ----
            float sc[2][8][4];
#pragma unroll
            for (int rf = 0; rf < 2; rf++)
#pragma unroll
                for (int nf = 0; nf < 8; nf++)
#pragma unroll
                    for (int c = 0; c < 4; c++) sc[rf][nf][c] = 0.0f;

#pragma unroll
            for (int jj = 0; jj < 8; jj++) {
                uint4 qa0 = *(const uint4*)&Qr[jj * 16];
                uint4 qa1 = *(const uint4*)&Qr[8 * DHD + jj * 16];
                uint4 qa2 = *(const uint4*)&Qr[16 * DHD + jj * 16];
                uint4 qa3 = *(const uint4*)&Qr[24 * DHD + jj * 16];
#pragma unroll
                for (int nf = 0; nf < 8; nf++) {
                    uint4 b = *(const uint4*)&Ks[(nf * 8 + gid) * KLD + jj * 16 + 4 * tid4];
                    mma_tf32(sc[0][nf], qa0.x, qa1.x, qa0.y, qa1.y, b.x, b.y);
                    mma_tf32(sc[0][nf], qa0.z, qa1.z, qa0.w, qa1.w, b.z, b.w);
                    mma_tf32(sc[1][nf], qa2.x, qa3.x, qa2.y, qa3.y, b.x, b.y);
                    mma_tf32(sc[1][nf], qa2.z, qa3.z, qa2.w, qa3.w, b.z, b.w);
                }
            }

            if (rel + 63 > mq) {  // some masking needed in this warp
#pragma unroll
                for (int rf = 0; rf < 2; rf++)
#pragma unroll
                    for (int nf = 0; nf < 8; nf++)
#pragma unroll
                        for (int c = 0; c < 4; c++) {
                            int col = nf * 8 + 2 * tid4 + (c & 1);
                            int row = mq + 16 * rf + gid + 8 * (c >> 1);
                            if (col + rel > row) sc[rf][nf][c] = -1e30f;
                        }
            }

            // ---- online softmax, 4 rows per lane ----
            float rm[4] = {-1e30f, -1e30f, -1e30f, -1e30f};
#pragma unroll
            for (int rf = 0; rf < 2; rf++)
#pragma unroll
                for (int nf = 0; nf < 8; nf++) {
                    rm[2 * rf + 0] = fmaxf(rm[2 * rf + 0], fmaxf(sc[rf][nf][0], sc[rf][nf][1]));
                    rm[2 * rf + 1] = fmaxf(rm[2 * rf + 1], fmaxf(sc[rf][nf][2], sc[rf][nf][3]));
                }
#pragma unroll
            for (int off = 1; off <= 2; off <<= 1)
#pragma unroll
                for (int r = 0; r < 4; r++)
                    rm[r] = fmaxf(rm[r], __shfl_xor_sync(0xffffffffu, rm[r], off));

            float alpha[4];
#pragma unroll
            for (int r = 0; r < 4; r++) {
                float mn = fmaxf(m_i[r], rm[r]);
                alpha[r] = fexp(m_i[r] - mn);
                m_i[r] = mn;
            }

            float rs[4] = {0.0f, 0.0f, 0.0f, 0.0f};
#pragma unroll
            for (int rf = 0; rf < 2; rf++)
#pragma unroll
                for (int nf = 0; nf < 8; nf++) {
                    float p0 = fexp(sc[rf][nf][0] - m_i[2 * rf + 0]);
                    float p1 = fexp(sc[rf][nf][1] - m_i[2 * rf + 0]);
                    float p2 = fexp(sc[rf][nf][2] - m_i[2 * rf + 1]);
                    float p3 = fexp(sc[rf][nf][3] - m_i[2 * rf + 1]);
                    rs[2 * rf + 0] += p0 + p1;
                    rs[2 * rf + 1] += p2 + p3;
                    int colb = nf * 8 + 2 * tid4;
                    uint2 u01; u01.x = to_tf32(p0); u01.y = to_tf32(p1);
                    uint2 u23; u23.x = to_tf32(p2); u23.y = to_tf32(p3);
                    *(uint2*)&Ps[(mq + 16 * rf + gid) * PLD + colb]     = u01;
                    *(uint2*)&Ps[(mq + 16 * rf + gid + 8) * PLD + colb] = u23;
                }
#pragma unroll
            for (int off = 1; off <= 2; off <<= 1)
#pragma unroll
                for (int r = 0; r < 4; r++)
                    rs[r] += __shfl_xor_sync(0xffffffffu, rs[r], off);
#pragma unroll
            for (int r = 0; r < 4; r++) l_i[r] = l_i[r] * alpha[r] + rs[r];

            // Rescale O (skip when all alphas are exactly 1)
            bool no_rescale = (alpha[0] == 1.0f) & (alpha[1] == 1.0f) &
                              (alpha[2] == 1.0f) & (alpha[3] == 1.0f);
            if (!__all_sync(0xffffffffu, no_rescale)) {
#pragma unroll
                for (int rf = 0; rf < 2; rf++)
#pragma unroll
                    for (int nf = 0; nf < 16; nf++) {
                        po[rf][nf][0] *= alpha[2 * rf + 0];
                        po[rf][nf][1] *= alpha[2 * rf + 0];
                        po[rf][nf][2] *= alpha[2 * rf + 1];
                        po[rf][nf][3] *= alpha[2 * rf + 1];
                    }
            }
            __syncwarp();  // P stores visible within warp
        }

        // prefetch K[kt+1] (hidden under PV)
        if (kt + 1 < nkt) FA_KPREF(kt + 1);

        if (warp_live) {
            // ---- O += P V : 32 rows x 128 d ----
#pragma unroll
            for (int jj = 0; jj < 4; jj++) {
                uint4 pa0 = *(const uint4*)&Ps[(mq + gid) * PLD + jj * 16 + 4 * tid4];
                uint4 pa1 = *(const uint4*)&Ps[(mq + gid + 8) * PLD + jj * 16 + 4 * tid4];
                uint4 pa2 = *(const uint4*)&Ps[(mq + 16 + gid) * PLD + jj * 16 + 4 * tid4];
                uint4 pa3 = *(const uint4*)&Ps[(mq + 24 + gid) * PLD + jj * 16 + 4 * tid4];
#pragma unroll
                for (int nf = 0; nf < 16; nf++) {
                    uint4 b = *(const uint4*)&vsb[(nf * 8 + gid) * VTLD + jj * 16 + 4 * tid4];
                    mma_tf32(po[0][nf], pa0.x, pa1.x, pa0.y, pa1.y, b.x, b.y);
                    mma_tf32(po[0][nf], pa0.z, pa1.z, pa0.w, pa1.w, b.z, b.w);
                    mma_tf32(po[1][nf], pa2.x, pa3.x, pa2.y, pa3.y, b.x, b.y);
                    mma_tf32(po[1][nf], pa2.z, pa3.z, pa2.w, pa3.w, b.z, b.w);
                }
            }
        }
    }
#undef FA_ISSUE_V
#undef FA_KPREF

    // Epilogue: normalize, convert to tf32 bits, write (b, s, d_model)
    float inv[4];
#pragma unroll
    for (int r = 0; r < 4; r++) inv[r] = 1.0f / l_i[r];
    int b  = bh >> 4;
    int hd = bh & 15;
#pragma unroll
    for (int rf = 0; rf < 2; rf++) {
        int row0 = q0 + mq + 16 * rf + gid;
#pragma unroll
        for (int nf = 0; nf < 16; nf++) {
            int col = hd * DHD + nf * 8 + 2 * tid4;
            uint2 u0, u1;
            u0.x = to_tf32(po[rf][nf][0] * inv[2 * rf + 0]);
            u0.y = to_tf32(po[rf][nf][1] * inv[2 * rf + 0]);
            u1.x = to_tf32(po[rf][nf][2] * inv[2 * rf + 1]);
            u1.y = to_tf32(po[rf][nf][3] * inv[2 * rf + 1]);
            *(uint2*)&Out[(size_t)(b * SS + row0) * D_MODEL + col]     = u0;
            *(uint2*)&Out[(size_t)(b * SS + row0 + 8) * D_MODEL + col] = u1;
        }
    }
}

// ---------------------------------------------------------------------------
extern "C" void kernel_launch(void* const* d_in, const int* in_sizes, int n_in,
                              void* d_out, int out_size) {
    const float* x  = (const float*)d_in[0];
    const float* pk = (const float*)d_in[1];
    const float* pv = (const float*)d_in[2];
    const float* Wq = (const float*)d_in[3];
    const float* Wk = (const float*)d_in[4];
    const float* Wv = (const float*)d_in[5];
    const float* Wo = (const float*)d_in[6];

    float* out = (float*)d_out;
    float* kc  = out + (size_t)BB * SS * D_MODEL;
    float* vc  = kc + (size_t)BHH * TOTAL * DHD;

    uint32_t *gXt, *gWt, *gQt, *gKt, *gVt, *gAt;
    cudaGetSymbolAddress((void**)&gXt, g_Xt);
    cudaGetSymbolAddress((void**)&gWt, g_Wt);
    cudaGetSymbolAddress((void**)&gQt, g_Qt);
    cudaGetSymbolAddress((void**)&gKt, g_Kt);
    cudaGetSymbolAddress((void**)&gVt, g_Vt);
    cudaGetSymbolAddress((void**)&gAt, g_At);

    cudaFuncSetAttribute(gemm_pipe_kernel<1>, cudaFuncAttributeMaxDynamicSharedMemorySize, GEMM_SMEM);
    cudaFuncSetAttribute(gemm_pipe_kernel<0>, cudaFuncAttributeMaxDynamicSharedMemorySize, GEMM_SMEM);
    cudaFuncSetAttribute(flash_attn_tc_kernel, cudaFuncAttributeMaxDynamicSharedMemorySize, FA_SMEM);

    // 1) prep
    cvt_x_kernel<<<(M_ROWS * D_MODEL / 4 + 255) / 256, 256>>>(
        (const float4*)x, (uint4*)gXt);
    cvt_w_kernel<<<dim3((D_MODEL * D_MODEL / 4 + 255) / 256, 4), 256>>>(
        (const float4*)Wq, (const float4*)Wk, (const float4*)Wv, (const float4*)Wo,
        (uint4*)gWt);
    copy_past_k_kernel<<<(BHH * PAST * DHD / 4 + 255) / 256, 256>>>(
        (const float4*)pk, (float4*)kc, (uint4*)gKt);
    transpose_past_v_kernel<<<dim3(PAST / 32, DHD / 32, BHH), 256>>>(
        pv, vc, gVt);

    // 2) fused Q/K/V projections
    dim3 qkv_grid(D_MODEL / 256, M_ROWS / 128, 3);  // (8, 32, 3)
    gemm_pipe_kernel<1><<<qkv_grid, 256, GEMM_SMEM>>>(
        gXt, gWt, nullptr, kc, vc, gQt, gKt, gVt);

    // 3) causal attention
    flash_attn_tc_kernel<<<dim3(SS / FBM, BHH), 256, FA_SMEM>>>(gQt, gKt, gVt, gAt);

    // 4) output projection
    dim3 o_grid(D_MODEL / 256, M_ROWS / 128, 1);
    gemm_pipe_kernel<0><<<o_grid, 256, GEMM_SMEM>>>(
        gAt, gWt + 3 * (size_t)D_MODEL * D_MODEL, out, nullptr, nullptr,
        nullptr, nullptr, nullptr);
}

// round 8
// speedup vs baseline: 1.2156x; 1.2156x over previous
#include <cuda_runtime.h>
#include <cstdint>

#define D_MODEL 2048
#define BB 2
#define SS 2048
#define HH 16
#define DHD 128
#define PAST 2048
#define TOTAL 4096
#define BHH 32
#define M_ROWS 4096
#define QK_SCALE 0.08838834764831845f

// Scratch (allocation-free rule: __device__ globals). All hold tf32 bit patterns.
__device__ uint32_t g_Xt[(size_t)M_ROWS * D_MODEL];
__device__ uint32_t g_Wt[4 * (size_t)D_MODEL * D_MODEL];
__device__ uint32_t g_Qt[(size_t)BHH * SS * DHD];        // (bh,s,dh), pre-scaled
__device__ uint32_t g_Kt[(size_t)BHH * TOTAL * DHD];     // (bh,key,dh)
__device__ uint32_t g_Vt[(size_t)BHH * DHD * TOTAL];     // V transposed (bh,dh,key)
__device__ uint32_t g_At[(size_t)BB * SS * D_MODEL];     // attn (b,s,dm)

// ---------------------------------------------------------------------------
// Helpers
// ---------------------------------------------------------------------------
__device__ __forceinline__ uint32_t to_tf32(float f) {
    uint32_t u;
    asm("cvt.rna.tf32.f32 %0, %1;" : "=r"(u) : "f"(f));
    return u;
}

__device__ __forceinline__ uint4 cvt4(float4 v) {
    uint4 r;
    r.x = to_tf32(v.x); r.y = to_tf32(v.y);
    r.z = to_tf32(v.z); r.w = to_tf32(v.w);
    return r;
}

__device__ __forceinline__ void mma_tf32(float* c,
                                         uint32_t a0, uint32_t a1, uint32_t a2, uint32_t a3,
                                         uint32_t b0, uint32_t b1) {
    asm volatile(
        "mma.sync.aligned.m16n8k8.row.col.f32.tf32.tf32.f32 "
        "{%0,%1,%2,%3}, {%4,%5,%6,%7}, {%8,%9}, {%0,%1,%2,%3};"
        : "+f"(c[0]), "+f"(c[1]), "+f"(c[2]), "+f"(c[3])
        : "r"(a0), "r"(a1), "r"(a2), "r"(a3), "r"(b0), "r"(b1));
}

// Fast exp on the FMA pipe (arg <= 0 always). fexp(0) == 1.0f exactly.
__device__ __forceinline__ float fexp(float x) {
    float t = fmaxf(x * 1.4426950408889634f, -126.0f);
    float r = t + 12582912.0f;
    float fn = r - 12582912.0f;
    float f = t - fn;
    int n = __float_as_int(r) - 0x4B400000;
    float p = 0.0013333558f;
    p = fmaf(p, f, 0.0096181291f);
    p = fmaf(p, f, 0.055504109f);
    p = fmaf(p, f, 0.24022651f);
    p = fmaf(p, f, 0.69314718f);
    p = fmaf(p, f, 1.0f);
    return p * __int_as_float((n + 127) << 23);
}

__device__ __forceinline__ void cpasync16(void* smem_dst, const void* gsrc) {
    uint32_t s = (uint32_t)__cvta_generic_to_shared(smem_dst);
    asm volatile("cp.async.cg.shared.global [%0], [%1], 16;" :: "r"(s), "l"(gsrc));
}
__device__ __forceinline__ void cpasync_commit() {
    asm volatile("cp.async.commit_group;");
}
__device__ __forceinline__ void cpasync_wait0() {
    asm volatile("cp.async.wait_group 0;");
}
__device__ __forceinline__ void cpasync_wait1() {
    asm volatile("cp.async.wait_group 1;");
}

// ---------------------------------------------------------------------------
// Prep kernels
// ---------------------------------------------------------------------------
__global__ void cvt_x_kernel(const float4* __restrict__ x, uint4* __restrict__ out) {
    int i = blockIdx.x * blockDim.x + threadIdx.x;
    if (i < M_ROWS * D_MODEL / 4) out[i] = cvt4(x[i]);
}

__global__ void cvt_w_kernel(const float4* __restrict__ w0, const float4* __restrict__ w1,
                             const float4* __restrict__ w2, const float4* __restrict__ w3,
                             uint4* __restrict__ out) {
    int z = blockIdx.y;
    const float4* src = (z == 0) ? w0 : (z == 1) ? w1 : (z == 2) ? w2 : w3;
    int i = blockIdx.x * blockDim.x + threadIdx.x;
    const int n4 = D_MODEL * D_MODEL / 4;
    if (i < n4) out[(size_t)z * n4 + i] = cvt4(src[i]);
}

__global__ void copy_past_k_kernel(const float4* __restrict__ pk,
                                   float4* __restrict__ kc, uint4* __restrict__ kt) {
    int i = blockIdx.x * blockDim.x + threadIdx.x;
    if (i >= BHH * PAST * DHD / 4) return;
    int bh  = i >> 16;
    int rem = i & 65535;
    int dst = (bh << 17) + rem;
    float4 v = pk[i];
    kc[dst] = v;
    kt[dst] = cvt4(v);
}

__global__ __launch_bounds__(256) void transpose_past_v_kernel(
    const float* __restrict__ pv, float* __restrict__ vc, uint32_t* __restrict__ vt) {
    __shared__ float ts[32][33];
    int bh = blockIdx.z;
    int k0 = blockIdx.x * 32;
    int d0 = blockIdx.y * 32;
    int tx = threadIdx.x & 31, ty = threadIdx.x >> 5;

    const float* src = pv + ((size_t)bh * PAST + k0) * DHD + d0;
    float* cdst      = vc + ((size_t)bh * TOTAL + k0) * DHD + d0;
#pragma unroll
    for (int j = 0; j < 4; j++) {
        int r = ty + 8 * j;
        float v = src[(size_t)r * DHD + tx];
        cdst[(size_t)r * DHD + tx] = v;
        ts[r][tx] = v;
    }
    __syncthreads();
    uint32_t* tdst = vt + (size_t)bh * DHD * TOTAL;
#pragma unroll
    for (int j = 0; j < 4; j++) {
        int d = d0 + ty + 8 * j;
        tdst[(size_t)d * TOTAL + k0 + tx] = to_tf32(ts[tx][ty + 8 * j]);
    }
}

// ---------------------------------------------------------------------------
// TF32 GEMM: CTA 256x128, 512 threads, 16 warps (4m x 4n), warp tile 64x32,
// BK=32, 2-stage cp.async (one barrier/iter). tf32-bit inputs.
// FUSED=1: z selects Wq/Wk/Wv + Q/KV epilogues. FUSED=0: row-major fp32 C.
// ---------------------------------------------------------------------------
#define GBM 256
#define GBN 128
#define GLDW 48
#define GSTAGE ((GBM + GBN) * GLDW)
#define GEMM_SMEM (2 * GSTAGE * 4)   // 147456 B

template <int FUSED>
__global__ __launch_bounds__(512) void gemm_pipe_kernel(
    const uint32_t* __restrict__ A, const uint32_t* __restrict__ Wt,
    float* __restrict__ C0, float* __restrict__ C1, float* __restrict__ C2,
    uint32_t* __restrict__ Qt, uint32_t* __restrict__ Kt, uint32_t* __restrict__ Vt) {
    extern __shared__ uint32_t smg[];

    int t    = threadIdx.x;
    int warp = t >> 5, lane = t & 31;
    int gid  = lane >> 2, tid4 = lane & 3;
    int wm   = (warp & 3) * 64;
    int wn   = (warp >> 2) * 32;
    int m0   = blockIdx.y * GBM;
    int n0   = blockIdx.x * GBN;
    int z    = FUSED ? blockIdx.z : 0;

    const uint32_t* Ab = A + (size_t)m0 * D_MODEL;
    const uint32_t* Bb = Wt + (FUSED ? (size_t)z * D_MODEL * D_MODEL : 0) + (size_t)n0 * D_MODEL;

    float acc[4][4][4];
#pragma unroll
    for (int mf = 0; mf < 4; mf++)
#pragma unroll
        for (int nf = 0; nf < 4; nf++)
#pragma unroll
            for (int c = 0; c < 4; c++) acc[mf][nf][c] = 0.0f;

    const int NT = D_MODEL / 32;  // 64

#define GEMM_ISSUE(KT, STG)                                                        \
    {                                                                              \
        uint32_t* As_ = smg + (STG) * GSTAGE;                                      \
        uint32_t* Bs_ = As_ + GBM * GLDW;                                          \
        const uint32_t* ab = Ab + (KT) * 32;                                       \
        const uint32_t* bb = Bb + (KT) * 32;                                       \
        _Pragma("unroll")                                                          \
        for (int j = 0; j < 4; j++) {                                              \
            int g  = t + 512 * j;                                                  \
            int r  = g >> 3;                                                       \
            int c4 = g & 7;                                                        \
            cpasync16(As_ + r * GLDW + c4 * 4, ab + (size_t)r * D_MODEL + c4 * 4); \
        }                                                                          \
        _Pragma("unroll")                                                          \
        for (int j = 0; j < 2; j++) {                                              \
            int g  = t + 512 * j;                                                  \
            int r  = g >> 3;                                                       \
            int c4 = g & 7;                                                        \
            cpasync16(Bs_ + r * GLDW + c4 * 4, bb + (size_t)r * D_MODEL + c4 * 4); \
        }                                                                          \
    }

    GEMM_ISSUE(0, 0); cpasync_commit();

    for (int kt = 0; kt < NT; kt++) {
        cpasync_wait0();       // stage kt&1 (group kt) complete
        __syncthreads();       // visible to all; prior readers of alt stage done
        if (kt + 1 < NT) {
            GEMM_ISSUE(kt + 1, (kt + 1) & 1);
            cpasync_commit();
        }

        const uint32_t* As = smg + (kt & 1) * GSTAGE;
        const uint32_t* Bs = As + GBM * GLDW;
#pragma unroll
        for (int jj = 0; jj < 2; jj++) {
            uint4 bq[4];
#pragma unroll
            for (int nf = 0; nf < 4; nf++)
                bq[nf] = *(const uint4*)&Bs[(wn + 8 * nf + gid) * GLDW + jj * 16 + tid4 * 4];
#pragma unroll
            for (int mf = 0; mf < 4; mf++) {
                uint4 al = *(const uint4*)&As[(wm + 16 * mf + gid) * GLDW + jj * 16 + tid4 * 4];
                uint4 ah = *(const uint4*)&As[(wm + 16 * mf + gid + 8) * GLDW + jj * 16 + tid4 * 4];
#pragma unroll
                for (int nf = 0; nf < 4; nf++) {
                    mma_tf32(acc[mf][nf], al.x, ah.x, al.y, ah.y, bq[nf].x, bq[nf].y);
                    mma_tf32(acc[mf][nf], al.z, ah.z, al.w, ah.w, bq[nf].z, bq[nf].w);
                }
            }
        }
        __syncthreads();       // all readers done before stage is overwritten
    }
#undef GEMM_ISSUE

    // Epilogue
#pragma unroll
    for (int mf = 0; mf < 4; mf++)
#pragma unroll
        for (int nf = 0; nf < 4; nf++)
#pragma unroll
            for (int h = 0; h < 2; h++) {
                int m = m0 + wm + 16 * mf + gid + 8 * h;
                int n = n0 + wn + 8 * nf + 2 * tid4;
                float2 v;
                v.x = acc[mf][nf][2 * h];
                v.y = acc[mf][nf][2 * h + 1];
                if (!FUSED) {
                    *(float2*)&C0[(size_t)m * D_MODEL + n] = v;
                } else {
                    int bb = m >> 11, ss = m & 2047;
                    int hd = n >> 7,  di = n & 127;
                    int bhh = bb * HH + hd;
                    if (z == 0) {
                        v.x *= QK_SCALE; v.y *= QK_SCALE;
                        uint2 u; u.x = to_tf32(v.x); u.y = to_tf32(v.y);
                        *(uint2*)&Qt[((size_t)bhh * SS + ss) * DHD + di] = u;
                    } else if (z == 1) {
                        size_t idx = ((size_t)bhh * TOTAL + (PAST + ss)) * DHD + di;
                        *(float2*)&C1[idx] = v;
                        uint2 u; u.x = to_tf32(v.x); u.y = to_tf32(v.y);
                        *(uint2*)&Kt[idx] = u;
                    } else {
                        size_t idx = ((size_t)bhh * TOTAL + (PAST + ss)) * DHD + di;
                        *(float2*)&C2[idx] = v;
                        size_t key = PAST + ss;
                        Vt[(size_t)bhh * DHD * TOTAL + (size_t)di * TOTAL + key]       = to_tf32(v.x);
                        Vt[(size_t)bhh * DHD * TOTAL + (size_t)(di + 1) * TOTAL + key] = to_tf32(v.y);
                    }
                }
            }
}

// ---------------------------------------------------------------------------
// Flash attention (round-6 proven version). tf32 mma. Q fragments in regs,
// K/Vt 2-stage cp.async, warp-private softmax, P smem-private.
// CTA: 128 q-rows x 64 keys/iter, 256 threads, 8 warps (warp w: rows w*16..+15).
// smem: Ks[2][64][144] + Vts[2][128][80] + Ps[128][80].
// ---------------------------------------------------------------------------
#define FBM 128
#define KLD 144
#define VTLD 80
#define PLD 80
#define FA_SMEM ((2 * 64 * KLD + 2 * 128 * VTLD + 128 * PLD) * 4)  // 196608

__global__ __launch_bounds__(256) void flash_attn_tc_kernel(
    const uint32_t* __restrict__ Qt, const uint32_t* __restrict__ Ktg,
    const uint32_t* __restrict__ Vtg, uint32_t* __restrict__ Out) {
    extern __shared__ uint32_t sm[];
    uint32_t* Ks  = sm;                      // [2][64][KLD]
    uint32_t* Vts = sm + 2 * 64 * KLD;       // [2][128][VTLD]
    uint32_t* Ps  = Vts + 2 * 128 * VTLD;    // [128][PLD]

    int t    = threadIdx.x;
    int warp = t >> 5, lane = t & 31;
    int gid  = lane >> 2, tid4 = lane & 3;
    int mq   = warp * 16;

    int bh = blockIdx.y;
    int q0 = (gridDim.x - 1 - blockIdx.x) * FBM;  // big tiles launch first

    const uint32_t* Kb = Ktg + (size_t)bh * TOTAL * DHD;
    const uint32_t* Vb = Vtg + (size_t)bh * DHD * TOTAL;

    // Q fragments in registers: rows mq+gid, mq+gid+8; k = jj*16 + 4*tid4 .. +3
    uint4 q0r[8], q1r[8];
    {
        const uint32_t* Qrow0 = Qt + ((size_t)bh * SS + (q0 + mq + gid)) * DHD + 4 * tid4;
        const uint32_t* Qrow1 = Qrow0 + 8 * DHD;
#pragma unroll
        for (int jj = 0; jj < 8; jj++) {
            q0r[jj] = *(const uint4*)&Qrow0[jj * 16];
            q1r[jj] = *(const uint4*)&Qrow1[jj * 16];
        }
    }

    float m0r = -1e30f, m1r = -1e30f, l0 = 0.0f, l1 = 0.0f;
    float po[16][4];
#pragma unroll
    for (int nf = 0; nf < 16; nf++)
#pragma unroll
        for (int c = 0; c < 4; c++) po[nf][c] = 0.0f;

#define FA_ISSUE(KT, STG)                                                          \
    {                                                                              \
        int k0_ = (KT) * 64;                                                       \
        uint32_t* ksd = Ks + (STG) * 64 * KLD;                                     \
        uint32_t* vsd = Vts + (STG) * 128 * VTLD;                                  \
        _Pragma("unroll")                                                          \
        for (int i = 0; i < 8; i++) {                                              \
            int id = t + 256 * i;                                                  \
            int r = id >> 5, c = id & 31;                                          \
            cpasync16(ksd + r * KLD + c * 4, Kb + (size_t)(k0_ + r) * DHD + c * 4);\
        }                                                                          \
        _Pragma("unroll")                                                          \
        for (int i = 0; i < 8; i++) {                                              \
            int id = t + 256 * i;                                                  \
            int d = id >> 4, kg = id & 15;                                         \
            cpasync16(vsd + d * VTLD + kg * 4, Vb + (size_t)d * TOTAL + k0_ + kg * 4); \
        }                                                                          \
    }

    int nkt = (PAST + q0 + FBM) / 64;
    FA_ISSUE(0, 0); cpasync_commit();

    for (int kt = 0; kt < nkt; kt++) {
        int k0 = kt * 64;
        bool masked = (k0 >= PAST + q0);
        int rel = k0 - PAST - q0;

        __syncthreads();  // all warps done reading stage (kt+1)&1 from iter kt-1
        if (kt + 1 < nkt) FA_ISSUE(kt + 1, (kt + 1) & 1);
        cpasync_commit();
        cpasync_wait1();
        __syncthreads();

        const uint32_t* ksb = Ks + (kt & 1) * 64 * KLD;
        const uint32_t* vsb = Vts + (kt & 1) * 128 * VTLD;

        // S = Q K^T : 16 rows x 64 keys
        float sc[8][4];
#pragma unroll
        for (int nf = 0; nf < 8; nf++)
#pragma unroll
            for (int c = 0; c < 4; c++) sc[nf][c] = 0.0f;

#pragma unroll
        for (int jj = 0; jj < 8; jj++) {
#pragma unroll
            for (int nf = 0; nf < 8; nf++) {
                uint4 b = *(const uint4*)&ksb[(nf * 8 + gid) * KLD + jj * 16 + 4 * tid4];
                mma_tf32(sc[nf], q0r[jj].x, q1r[jj].x, q0r[jj].y, q1r[jj].y, b.x, b.y);
                mma_tf32(sc[nf], q0r[jj].z, q1r[jj].z, q0r[jj].w, q1r[jj].w, b.z, b.w);
            }
        }

        if (masked) {
#pragma unroll
            for (int nf = 0; nf < 8; nf++)
#pragma unroll
                for (int c = 0; c < 4; c++) {
                    int col = nf * 8 + 2 * tid4 + (c & 1);
                    int row = mq + gid + 8 * (c >> 1);
                    if (col + rel > row) sc[nf][c] = -1e30f;
                }
        }

        // Warp-private online softmax (rows mq+gid, mq+gid+8)
        float rm0 = -1e30f, rm1 = -1e30f;
#pragma unroll
        for (int nf = 0; nf < 8; nf++) {
            rm0 = fmaxf(rm0, fmaxf(sc[nf][0], sc[nf][1]));
            rm1 = fmaxf(rm1, fmaxf(sc[nf][2], sc[nf][3]));
        }
#pragma unroll
        for (int off = 1; off <= 2; off <<= 1) {
            rm0 = fmaxf(rm0, __shfl_xor_sync(0xffffffffu, rm0, off));
            rm1 = fmaxf(rm1, __shfl_xor_sync(0xffffffffu, rm1, off));
        }
        float mn0 = fmaxf(m0r, rm0);
        float mn1 = fmaxf(m1r, rm1);
        float alpha0 = fexp(m0r - mn0);
        float alpha1 = fexp(m1r - mn1);
        m0r = mn0; m1r = mn1;

        __syncwarp();  // prior PV reads of Ps complete before overwrite
        float rs0 = 0.0f, rs1 = 0.0f;
#pragma unroll
        for (int nf = 0; nf < 8; nf++) {
            float p0 = fexp(sc[nf][0] - mn0);
            float p1 = fexp(sc[nf][1] - mn0);
            float p2 = fexp(sc[nf][2] - mn1);
            float p3 = fexp(sc[nf][3] - mn1);
            rs0 += p0 + p1;
            rs1 += p2 + p3;
            int colb = nf * 8 + 2 * tid4;
            uint2 u01; u01.x = to_tf32(p0); u01.y = to_tf32(p1);
            uint2 u23; u23.x = to_tf32(p2); u23.y = to_tf32(p3);
            *(uint2*)&Ps[(mq + gid) * PLD + colb]     = u01;
            *(uint2*)&Ps[(mq + gid + 8) * PLD + colb] = u23;
        }
#pragma unroll
        for (int off = 1; off <= 2; off <<= 1) {
            rs0 += __shfl_xor_sync(0xffffffffu, rs0, off);
            rs1 += __shfl_xor_sync(0xffffffffu, rs1, off);
        }
        l0 = l0 * alpha0 + rs0;
        l1 = l1 * alpha1 + rs1;

        // Rescale O (skip when both alphas are exactly 1 across the warp)
        bool no_rescale = (alpha0 == 1.0f) & (alpha1 == 1.0f);
        if (!__all_sync(0xffffffffu, no_rescale)) {
#pragma unroll
            for (int nf = 0; nf < 16; nf++) {
                po[nf][0] *= alpha0; po[nf][1] *= alpha0;
                po[nf][2] *= alpha1; po[nf][3] *= alpha1;
            }
        }
        __syncwarp();  // P stores visible to warp

        // O += P V : A = Ps fragments, B = Vt (d-major, key-vectorized)
#pragma unroll
        for (int jj = 0; jj < 4; jj++) {
            uint4 pa0 = *(const uint4*)&Ps[(mq + gid) * PLD + jj * 16 + 4 * tid4];
            uint4 pa1 = *(const uint4*)&Ps[(mq + gid + 8) * PLD + jj * 16 + 4 * tid4];
#pragma unroll
            for (int nf = 0; nf < 16; nf++) {
                uint4 b = *(const uint4*)&vsb[(nf * 8 + gid) * VTLD + jj * 16 + 4 * tid4];
                mma_tf32(po[nf], pa0.x, pa1.x, pa0.y, pa1.y, b.x, b.y);
                mma_tf32(po[nf], pa0.z, pa1.z, pa0.w, pa1.w, b.z, b.w);
            }
        }
    }
#undef FA_ISSUE

    // Epilogue: normalize, convert to tf32 bits, write (b, s, d_model)
    float inv0 = 1.0f / l0;
    float inv1 = 1.0f / l1;
    int b  = bh >> 4;
    int hd = bh & 15;
    int row0 = q0 + mq + gid;
    int row1 = row0 + 8;
#pragma unroll
    for (int nf = 0; nf < 16; nf++) {
        int col = hd * DHD + nf * 8 + 2 * tid4;
        uint2 u0, u1;
        u0.x = to_tf32(po[nf][0] * inv0); u0.y = to_tf32(po[nf][1] * inv0);
        u1.x = to_tf32(po[nf][2] * inv1); u1.y = to_tf32(po[nf][3] * inv1);
        *(uint2*)&Out[(size_t)(b * SS + row0) * D_MODEL + col] = u0;
        *(uint2*)&Out[(size_t)(b * SS + row1) * D_MODEL + col] = u1;
    }
}

// ---------------------------------------------------------------------------
extern "C" void kernel_launch(void* const* d_in, const int* in_sizes, int n_in,
                              void* d_out, int out_size) {
    const float* x  = (const float*)d_in[0];
    const float* pk = (const float*)d_in[1];
    const float* pv = (const float*)d_in[2];
    const float* Wq = (const float*)d_in[3];
    const float* Wk = (const float*)d_in[4];
    const float* Wv = (const float*)d_in[5];
    const float* Wo = (const float*)d_in[6];

    float* out = (float*)d_out;
    float* kc  = out + (size_t)BB * SS * D_MODEL;
    float* vc  = kc + (size_t)BHH * TOTAL * DHD;

    uint32_t *gXt, *gWt, *gQt, *gKt, *gVt, *gAt;
    cudaGetSymbolAddress((void**)&gXt, g_Xt);
    cudaGetSymbolAddress((void**)&gWt, g_Wt);
    cudaGetSymbolAddress((void**)&gQt, g_Qt);
    cudaGetSymbolAddress((void**)&gKt, g_Kt);
    cudaGetSymbolAddress((void**)&gVt, g_Vt);
    cudaGetSymbolAddress((void**)&gAt, g_At);

    cudaFuncSetAttribute(gemm_pipe_kernel<1>, cudaFuncAttributeMaxDynamicSharedMemorySize, GEMM_SMEM);
    cudaFuncSetAttribute(gemm_pipe_kernel<0>, cudaFuncAttributeMaxDynamicSharedMemorySize, GEMM_SMEM);
    cudaFuncSetAttribute(flash_attn_tc_kernel, cudaFuncAttributeMaxDynamicSharedMemorySize, FA_SMEM);

    // 1) prep
    cvt_x_kernel<<<(M_ROWS * D_MODEL / 4 + 255) / 256, 256>>>(
        (const float4*)x, (uint4*)gXt);
    cvt_w_kernel<<<dim3((D_MODEL * D_MODEL / 4 + 255) / 256, 4), 256>>>(
        (const float4*)Wq, (const float4*)Wk, (const float4*)Wv, (const float4*)Wo,
        (uint4*)gWt);
    copy_past_k_kernel<<<(BHH * PAST * DHD / 4 + 255) / 256, 256>>>(
        (const float4*)pk, (float4*)kc, (uint4*)gKt);
    transpose_past_v_kernel<<<dim3(PAST / 32, DHD / 32, BHH), 256>>>(
        pv, vc, gVt);

    // 2) fused Q/K/V projections (16 warps/CTA, 2-stage)
    dim3 qkv_grid(D_MODEL / GBN, M_ROWS / GBM, 3);  // (16, 16, 3)
    gemm_pipe_kernel<1><<<qkv_grid, 512, GEMM_SMEM>>>(
        gXt, gWt, nullptr, kc, vc, gQt, gKt, gVt);

    // 3) causal attention
    flash_attn_tc_kernel<<<dim3(SS / FBM, BHH), 256, FA_SMEM>>>(gQt, gKt, gVt, gAt);

    // 4) output projection
    dim3 o_grid(D_MODEL / GBN, M_ROWS / GBM, 1);
    gemm_pipe_kernel<0><<<o_grid, 512, GEMM_SMEM>>>(
        gAt, gWt + 3 * (size_t)D_MODEL * D_MODEL, out, nullptr, nullptr,
        nullptr, nullptr, nullptr);
}

// round 9
// speedup vs baseline: 1.2774x; 1.0509x over previous
#include <cuda_runtime.h>
#include <cstdint>

#define D_MODEL 2048
#define BB 2
#define SS 2048
#define HH 16
#define DHD 128
#define PAST 2048
#define TOTAL 4096
#define BHH 32
#define M_ROWS 4096
// 1/sqrt(128) * log2(e): scores land in log2 domain -> softmax via EX2 only
#define QK_SCALE_L2E ((float)(0.08838834764831845 * 1.4426950408889634))

// Scratch (allocation-free rule: __device__ globals). All hold tf32 bit patterns.
__device__ uint32_t g_Xt[(size_t)M_ROWS * D_MODEL];
__device__ uint32_t g_Wt[4 * (size_t)D_MODEL * D_MODEL];
__device__ uint32_t g_Qt[(size_t)BHH * SS * DHD];        // (bh,s,dh), pre-scaled by QK_SCALE_L2E
__device__ uint32_t g_Kt[(size_t)BHH * TOTAL * DHD];     // (bh,key,dh)
__device__ uint32_t g_Vt[(size_t)BHH * DHD * TOTAL];     // V transposed (bh,dh,key)
__device__ uint32_t g_At[(size_t)BB * SS * D_MODEL];     // attn (b,s,dm)

// ---------------------------------------------------------------------------
// Helpers
// ---------------------------------------------------------------------------
__device__ __forceinline__ uint32_t to_tf32(float f) {
    uint32_t u;
    asm("cvt.rna.tf32.f32 %0, %1;" : "=r"(u) : "f"(f));
    return u;
}

__device__ __forceinline__ uint4 cvt4(float4 v) {
    uint4 r;
    r.x = to_tf32(v.x); r.y = to_tf32(v.y);
    r.z = to_tf32(v.z); r.w = to_tf32(v.w);
    return r;
}

__device__ __forceinline__ void mma_tf32(float* c,
                                         uint32_t a0, uint32_t a1, uint32_t a2, uint32_t a3,
                                         uint32_t b0, uint32_t b1) {
    asm volatile(
        "mma.sync.aligned.m16n8k8.row.col.f32.tf32.tf32.f32 "
        "{%0,%1,%2,%3}, {%4,%5,%6,%7}, {%8,%9}, {%0,%1,%2,%3};"
        : "+f"(c[0]), "+f"(c[1]), "+f"(c[2]), "+f"(c[3])
        : "r"(a0), "r"(a1), "r"(a2), "r"(a3), "r"(b0), "r"(b1));
}

// exp2 on MUFU: 1 issue slot. ex2(0) == 1.0f exactly.
__device__ __forceinline__ float ex2(float x) {
    float r;
    asm("ex2.approx.ftz.f32 %0, %1;" : "=f"(r) : "f"(x));
    return r;
}

__device__ __forceinline__ void cpasync16(void* smem_dst, const void* gsrc) {
    uint32_t s = (uint32_t)__cvta_generic_to_shared(smem_dst);
    asm volatile("cp.async.cg.shared.global [%0], [%1], 16;" :: "r"(s), "l"(gsrc));
}
__device__ __forceinline__ void cpasync_commit() {
    asm volatile("cp.async.commit_group;");
}
__device__ __forceinline__ void cpasync_wait1() {
    asm volatile("cp.async.wait_group 1;");
}

// ---------------------------------------------------------------------------
// Prep kernels
// ---------------------------------------------------------------------------
__global__ void cvt_x_kernel(const float4* __restrict__ x, uint4* __restrict__ out) {
    int i = blockIdx.x * blockDim.x + threadIdx.x;
    if (i < M_ROWS * D_MODEL / 4) out[i] = cvt4(x[i]);
}

__global__ void cvt_w_kernel(const float4* __restrict__ w0, const float4* __restrict__ w1,
                             const float4* __restrict__ w2, const float4* __restrict__ w3,
                             uint4* __restrict__ out) {
    int z = blockIdx.y;
    const float4* src = (z == 0) ? w0 : (z == 1) ? w1 : (z == 2) ? w2 : w3;
    int i = blockIdx.x * blockDim.x + threadIdx.x;
    const int n4 = D_MODEL * D_MODEL / 4;
    if (i < n4) out[(size_t)z * n4 + i] = cvt4(src[i]);
}

__global__ void copy_past_k_kernel(const float4* __restrict__ pk,
                                   float4* __restrict__ kc, uint4* __restrict__ kt) {
    int i = blockIdx.x * blockDim.x + threadIdx.x;
    if (i >= BHH * PAST * DHD / 4) return;
    int bh  = i >> 16;
    int rem = i & 65535;
    int dst = (bh << 17) + rem;
    float4 v = pk[i];
    kc[dst] = v;
    kt[dst] = cvt4(v);
}

__global__ __launch_bounds__(256) void transpose_past_v_kernel(
    const float* __restrict__ pv, float* __restrict__ vc, uint32_t* __restrict__ vt) {
    __shared__ float ts[32][33];
    int bh = blockIdx.z;
    int k0 = blockIdx.x * 32;
    int d0 = blockIdx.y * 32;
    int tx = threadIdx.x & 31, ty = threadIdx.x >> 5;

    const float* src = pv + ((size_t)bh * PAST + k0) * DHD + d0;
    float* cdst      = vc + ((size_t)bh * TOTAL + k0) * DHD + d0;
#pragma unroll
    for (int j = 0; j < 4; j++) {
        int r = ty + 8 * j;
        float v = src[(size_t)r * DHD + tx];
        cdst[(size_t)r * DHD + tx] = v;
        ts[r][tx] = v;
    }
    __syncthreads();
    uint32_t* tdst = vt + (size_t)bh * DHD * TOTAL;
#pragma unroll
    for (int j = 0; j < 4; j++) {
        int d = d0 + ty + 8 * j;
        tdst[(size_t)d * TOTAL + k0 + tx] = to_tf32(ts[tx][ty + 8 * j]);
    }
}

// ---------------------------------------------------------------------------
// TF32 GEMM: CTA 256x128, 512 threads, 16 warps (4m x 4n), warp tile 64x32,
// BK=32, 3-stage cp.async (ONE barrier/iter). tf32-bit inputs.
// FUSED=1: z selects Wq/Wk/Wv + Q/KV epilogues. FUSED=0: row-major fp32 C.
// ---------------------------------------------------------------------------
#define GBM 256
#define GBN 128
#define GLDW 48
#define GSTAGE ((GBM + GBN) * GLDW)
#define GEMM_SMEM (3 * GSTAGE * 4)   // 221184 B

template <int FUSED>
__global__ __launch_bounds__(512) void gemm_pipe_kernel(
    const uint32_t* __restrict__ A, const uint32_t* __restrict__ Wt,
    float* __restrict__ C0, float* __restrict__ C1, float* __restrict__ C2,
    uint32_t* __restrict__ Qt, uint32_t* __restrict__ Kt, uint32_t* __restrict__ Vt) {
    extern __shared__ uint32_t smg[];

    int t    = threadIdx.x;
    int warp = t >> 5, lane = t & 31;
    int gid  = lane >> 2, tid4 = lane & 3;
    int wm   = (warp & 3) * 64;
    int wn   = (warp >> 2) * 32;
    int m0   = blockIdx.y * GBM;
    int n0   = blockIdx.x * GBN;
    int z    = FUSED ? blockIdx.z : 0;

    const uint32_t* Ab = A + (size_t)m0 * D_MODEL;
    const uint32_t* Bb = Wt + (FUSED ? (size_t)z * D_MODEL * D_MODEL : 0) + (size_t)n0 * D_MODEL;

    float acc[4][4][4];
#pragma unroll
    for (int mf = 0; mf < 4; mf++)
#pragma unroll
        for (int nf = 0; nf < 4; nf++)
#pragma unroll
            for (int c = 0; c < 4; c++) acc[mf][nf][c] = 0.0f;

    const int NT = D_MODEL / 32;  // 64

#define GEMM_ISSUE(KT, STG)                                                        \
    {                                                                              \
        uint32_t* As_ = smg + (STG) * GSTAGE;                                      \
        uint32_t* Bs_ = As_ + GBM * GLDW;                                          \
        const uint32_t* ab = Ab + (KT) * 32;                                       \
        const uint32_t* bb = Bb + (KT) * 32;                                       \
        _Pragma("unroll")                                                          \
        for (int j = 0; j < 4; j++) {                                              \
            int g  = t + 512 * j;                                                  \
            int r  = g >> 3;                                                       \
            int c4 = g & 7;                                                        \
            cpasync16(As_ + r * GLDW + c4 * 4, ab + (size_t)r * D_MODEL + c4 * 4); \
        }                                                                          \
        _Pragma("unroll")                                                          \
        for (int j = 0; j < 2; j++) {                                              \
            int g  = t + 512 * j;                                                  \
            int r  = g >> 3;                                                       \
            int c4 = g & 7;                                                        \
            cpasync16(Bs_ + r * GLDW + c4 * 4, bb + (size_t)r * D_MODEL + c4 * 4); \
        }                                                                          \
    }

    GEMM_ISSUE(0, 0); cpasync_commit();
    GEMM_ISSUE(1, 1); cpasync_commit();

    for (int kt = 0; kt < NT; kt++) {
        cpasync_wait1();       // stage kt%3 complete
        __syncthreads();       // all warps done with stage (kt+2)%3 reads (iter kt-1)
        if (kt + 2 < NT) GEMM_ISSUE(kt + 2, (kt + 2) % 3);
        cpasync_commit();

        const uint32_t* As = smg + (kt % 3) * GSTAGE;
        const uint32_t* Bs = As + GBM * GLDW;
#pragma unroll
        for (int jj = 0; jj < 2; jj++) {
            uint4 bq[4];
#pragma unroll
            for (int nf = 0; nf < 4; nf++)
                bq[nf] = *(const uint4*)&Bs[(wn + 8 * nf + gid) * GLDW + jj * 16 + tid4 * 4];
#pragma unroll
            for (int mf = 0; mf < 4; mf++) {
                uint4 al = *(const uint4*)&As[(wm + 16 * mf + gid) * GLDW + jj * 16 + tid4 * 4];
                uint4 ah = *(const uint4*)&As[(wm + 16 * mf + gid + 8) * GLDW + jj * 16 + tid4 * 4];
#pragma unroll
                for (int nf = 0; nf < 4; nf++) {
                    mma_tf32(acc[mf][nf], al.x, ah.x, al.y, ah.y, bq[nf].x, bq[nf].y);
                    mma_tf32(acc[mf][nf], al.z, ah.z, al.w, ah.w, bq[nf].z, bq[nf].w);
                }
            }
        }
    }
#undef GEMM_ISSUE

    // Epilogue
#pragma unroll
    for (int mf = 0; mf < 4; mf++)
#pragma unroll
        for (int nf = 0; nf < 4; nf++)
#pragma unroll
            for (int h = 0; h < 2; h++) {
                int m = m0 + wm + 16 * mf + gid + 8 * h;
                int n = n0 + wn + 8 * nf + 2 * tid4;
                float2 v;
                v.x = acc[mf][nf][2 * h];
                v.y = acc[mf][nf][2 * h + 1];
                if (!FUSED) {
                    *(float2*)&C0[(size_t)m * D_MODEL + n] = v;
                } else {
                    int bb = m >> 11, ss = m & 2047;
                    int hd = n >> 7,  di = n & 127;
                    int bhh = bb * HH + hd;
                    if (z == 0) {
                        v.x *= QK_SCALE_L2E; v.y *= QK_SCALE_L2E;
                        uint2 u; u.x = to_tf32(v.x); u.y = to_tf32(v.y);
                        *(uint2*)&Qt[((size_t)bhh * SS + ss) * DHD + di] = u;
                    } else if (z == 1) {
                        size_t idx = ((size_t)bhh * TOTAL + (PAST + ss)) * DHD + di;
                        *(float2*)&C1[idx] = v;
                        uint2 u; u.x = to_tf32(v.x); u.y = to_tf32(v.y);
                        *(uint2*)&Kt[idx] = u;
                    } else {
                        size_t idx = ((size_t)bhh * TOTAL + (PAST + ss)) * DHD + di;
                        *(float2*)&C2[idx] = v;
                        size_t key = PAST + ss;
                        Vt[(size_t)bhh * DHD * TOTAL + (size_t)di * TOTAL + key]       = to_tf32(v.x);
                        Vt[(size_t)bhh * DHD * TOTAL + (size_t)(di + 1) * TOTAL + key] = to_tf32(v.y);
                    }
                }
            }
}

// ---------------------------------------------------------------------------
// Flash attention. tf32 mma, EX2-only softmax (scores pre-scaled to log2).
// Q fragments in regs, K/Vt 2-stage cp.async, warp-private softmax, P smem.
// CTA: 128 q-rows x 64 keys/iter, 256 threads, 8 warps (warp w: rows w*16..+15).
// smem: Ks[2][64][144] + Vts[2][128][80] + Ps[128][80].
// ---------------------------------------------------------------------------
#define FBM 128
#define KLD 144
#define VTLD 80
#define PLD 80
#define FA_SMEM ((2 * 64 * KLD + 2 * 128 * VTLD + 128 * PLD) * 4)  // 196608

__global__ __launch_bounds__(256) void flash_attn_tc_kernel(
    const uint32_t* __restrict__ Qt, const uint32_t* __restrict__ Ktg,
    const uint32_t* __restrict__ Vtg, uint32_t* __restrict__ Out) {
    extern __shared__ uint32_t sm[];
    uint32_t* Ks  = sm;                      // [2][64][KLD]
    uint32_t* Vts = sm + 2 * 64 * KLD;       // [2][128][VTLD]
    uint32_t* Ps  = Vts + 2 * 128 * VTLD;    // [128][PLD]

    int t    = threadIdx.x;
    int warp = t >> 5, lane = t & 31;
    int gid  = lane >> 2, tid4 = lane & 3;
    int mq   = warp * 16;

    int bh = blockIdx.y;
    int q0 = (gridDim.x - 1 - blockIdx.x) * FBM;  // big tiles launch first

    const uint32_t* Kb = Ktg + (size_t)bh * TOTAL * DHD;
    const uint32_t* Vb = Vtg + (size_t)bh * DHD * TOTAL;

    // Q fragments in registers: rows mq+gid, mq+gid+8; k = jj*16 + 4*tid4 .. +3
    uint4 q0r[8], q1r[8];
    {
        const uint32_t* Qrow0 = Qt + ((size_t)bh * SS + (q0 + mq + gid)) * DHD + 4 * tid4;
        const uint32_t* Qrow1 = Qrow0 + 8 * DHD;
#pragma unroll
        for (int jj = 0; jj < 8; jj++) {
            q0r[jj] = *(const uint4*)&Qrow0[jj * 16];
            q1r[jj] = *(const uint4*)&Qrow1[jj * 16];
        }
    }

    float m0r = -1e30f, m1r = -1e30f, l0 = 0.0f, l1 = 0.0f;
    float po[16][4];
#pragma unroll
    for (int nf = 0; nf < 16; nf++)
#pragma unroll
        for (int c = 0; c < 4; c++) po[nf][c] = 0.0f;

#define FA_ISSUE(KT, STG)                                                          \
    {                                                                              \
        int k0_ = (KT) * 64;                                                       \
        uint32_t* ksd = Ks + (STG) * 64 * KLD;                                     \
        uint32_t* vsd = Vts + (STG) * 128 * VTLD;                                  \
        _Pragma("unroll")                                                          \
        for (int i = 0; i < 8; i++) {                                              \
            int id = t + 256 * i;                                                  \
            int r = id >> 5, c = id & 31;                                          \
            cpasync16(ksd + r * KLD + c * 4, Kb + (size_t)(k0_ + r) * DHD + c * 4);\
        }                                                                          \
        _Pragma("unroll")                                                          \
        for (int i = 0; i < 8; i++) {                                              \
            int id = t + 256 * i;                                                  \
            int d = id >> 4, kg = id & 15;                                         \
            cpasync16(vsd + d * VTLD + kg * 4, Vb + (size_t)d * TOTAL + k0_ + kg * 4); \
        }                                                                          \
    }

    int nkt = (PAST + q0 + FBM) / 64;
    FA_ISSUE(0, 0); cpasync_commit();

    for (int kt = 0; kt < nkt; kt++) {
        int k0 = kt * 64;
        bool masked = (k0 >= PAST + q0);
        int rel = k0 - PAST - q0;

        __syncthreads();  // all warps done reading stage (kt+1)&1 from iter kt-1
        if (kt + 1 < nkt) FA_ISSUE(kt + 1, (kt + 1) & 1);
        cpasync_commit();
        cpasync_wait1();
        __syncthreads();

        const uint32_t* ksb = Ks + (kt & 1) * 64 * KLD;
        const uint32_t* vsb = Vts + (kt & 1) * 128 * VTLD;

        // S = Q K^T : 16 rows x 64 keys (log2-domain scores)
        float sc[8][4];
#pragma unroll
        for (int nf = 0; nf < 8; nf++)
#pragma unroll
            for (int c = 0; c < 4; c++) sc[nf][c] = 0.0f;

#pragma unroll
        for (int jj = 0; jj < 8; jj++) {
#pragma unroll
            for (int nf = 0; nf < 8; nf++) {
                uint4 b = *(const uint4*)&ksb[(nf * 8 + gid) * KLD + jj * 16 + 4 * tid4];
                mma_tf32(sc[nf], q0r[jj].x, q1r[jj].x, q0r[jj].y, q1r[jj].y, b.x, b.y);
                mma_tf32(sc[nf], q0r[jj].z, q1r[jj].z, q0r[jj].w, q1r[jj].w, b.z, b.w);
            }
        }

        if (masked) {
#pragma unroll
            for (int nf = 0; nf < 8; nf++)
#pragma unroll
                for (int c = 0; c < 4; c++) {
                    int col = nf * 8 + 2 * tid4 + (c & 1);
                    int row = mq + gid + 8 * (c >> 1);
                    if (col + rel > row) sc[nf][c] = -1e30f;
                }
        }

        // Warp-private online softmax (rows mq+gid, mq+gid+8), EX2 only
        float rm0 = -1e30f, rm1 = -1e30f;
#pragma unroll
        for (int nf = 0; nf < 8; nf++) {
            rm0 = fmaxf(rm0, fmaxf(sc[nf][0], sc[nf][1]));
            rm1 = fmaxf(rm1, fmaxf(sc[nf][2], sc[nf][3]));
        }
#pragma unroll
        for (int off = 1; off <= 2; off <<= 1) {
            rm0 = fmaxf(rm0, __shfl_xor_sync(0xffffffffu, rm0, off));
            rm1 = fmaxf(rm1, __shfl_xor_sync(0xffffffffu, rm1, off));
        }
        float mn0 = fmaxf(m0r, rm0);
        float mn1 = fmaxf(m1r, rm1);
        float alpha0 = ex2(m0r - mn0);
        float alpha1 = ex2(m1r - mn1);
        m0r = mn0; m1r = mn1;

        __syncwarp();  // prior PV reads of Ps complete before overwrite
        float rs0 = 0.0f, rs1 = 0.0f;
#pragma unroll
        for (int nf = 0; nf < 8; nf++) {
            float p0 = ex2(sc[nf][0] - mn0);
            float p1 = ex2(sc[nf][1] - mn0);
            float p2 = ex2(sc[nf][2] - mn1);
            float p3 = ex2(sc[nf][3] - mn1);
            rs0 += p0 + p1;
            rs1 += p2 + p3;
            int colb = nf * 8 + 2 * tid4;
            uint2 u01; u01.x = to_tf32(p0); u01.y = to_tf32(p1);
            uint2 u23; u23.x = to_tf32(p2); u23.y = to_tf32(p3);
            *(uint2*)&Ps[(mq + gid) * PLD + colb]     = u01;
            *(uint2*)&Ps[(mq + gid + 8) * PLD + colb] = u23;
        }
#pragma unroll
        for (int off = 1; off <= 2; off <<= 1) {
            rs0 += __shfl_xor_sync(0xffffffffu, rs0, off);
            rs1 += __shfl_xor_sync(0xffffffffu, rs1, off);
        }
        l0 = l0 * alpha0 + rs0;
        l1 = l1 * alpha1 + rs1;

        // Rescale O (skip when both alphas are exactly 1 across the warp)
        bool no_rescale = (alpha0 == 1.0f) & (alpha1 == 1.0f);
        if (!__all_sync(0xffffffffu, no_rescale)) {
#pragma unroll
            for (int nf = 0; nf < 16; nf++) {
                po[nf][0] *= alpha0; po[nf][1] *= alpha0;
                po[nf][2] *= alpha1; po[nf][3] *= alpha1;
            }
        }
        __syncwarp();  // P stores visible to warp

        // O += P V : A = Ps fragments, B = Vt (d-major, key-vectorized)
#pragma unroll
        for (int jj = 0; jj < 4; jj++) {
            uint4 pa0 = *(const uint4*)&Ps[(mq + gid) * PLD + jj * 16 + 4 * tid4];
            uint4 pa1 = *(const uint4*)&Ps[(mq + gid + 8) * PLD + jj * 16 + 4 * tid4];
#pragma unroll
            for (int nf = 0; nf < 16; nf++) {
                uint4 b = *(const uint4*)&vsb[(nf * 8 + gid) * VTLD + jj * 16 + 4 * tid4];
                mma_tf32(po[nf], pa0.x, pa1.x, pa0.y, pa1.y, b.x, b.y);
                mma_tf32(po[nf], pa0.z, pa1.z, pa0.w, pa1.w, b.z, b.w);
            }
        }
    }
#undef FA_ISSUE

    // Epilogue: normalize, convert to tf32 bits, write (b, s, d_model)
    float inv0 = 1.0f / l0;
    float inv1 = 1.0f / l1;
    int b  = bh >> 4;
    int hd = bh & 15;
    int row0 = q0 + mq + gid;
    int row1 = row0 + 8;
#pragma unroll
    for (int nf = 0; nf < 16; nf++) {
        int col = hd * DHD + nf * 8 + 2 * tid4;
        uint2 u0, u1;
        u0.x = to_tf32(po[nf][0] * inv0); u0.y = to_tf32(po[nf][1] * inv0);
        u1.x = to_tf32(po[nf][2] * inv1); u1.y = to_tf32(po[nf][3] * inv1);
        *(uint2*)&Out[(size_t)(b * SS + row0) * D_MODEL + col] = u0;
        *(uint2*)&Out[(size_t)(b * SS + row1) * D_MODEL + col] = u1;
    }
}

// ---------------------------------------------------------------------------
extern "C" void kernel_launch(void* const* d_in, const int* in_sizes, int n_in,
                              void* d_out, int out_size) {
    const float* x  = (const float*)d_in[0];
    const float* pk = (const float*)d_in[1];
    const float* pv = (const float*)d_in[2];
    const float* Wq = (const float*)d_in[3];
    const float* Wk = (const float*)d_in[4];
    const float* Wv = (const float*)d_in[5];
    const float* Wo = (const float*)d_in[6];

    float* out = (float*)d_out;
    float* kc  = out + (size_t)BB * SS * D_MODEL;
    float* vc  = kc + (size_t)BHH * TOTAL * DHD;

    uint32_t *gXt, *gWt, *gQt, *gKt, *gVt, *gAt;
    cudaGetSymbolAddress((void**)&gXt, g_Xt);
    cudaGetSymbolAddress((void**)&gWt, g_Wt);
    cudaGetSymbolAddress((void**)&gQt, g_Qt);
    cudaGetSymbolAddress((void**)&gKt, g_Kt);
    cudaGetSymbolAddress((void**)&gVt, g_Vt);
    cudaGetSymbolAddress((void**)&gAt, g_At);

    cudaFuncSetAttribute(gemm_pipe_kernel<1>, cudaFuncAttributeMaxDynamicSharedMemorySize, GEMM_SMEM);
    cudaFuncSetAttribute(gemm_pipe_kernel<0>, cudaFuncAttributeMaxDynamicSharedMemorySize, GEMM_SMEM);
    cudaFuncSetAttribute(flash_attn_tc_kernel, cudaFuncAttributeMaxDynamicSharedMemorySize, FA_SMEM);

    // 1) prep
    cvt_x_kernel<<<(M_ROWS * D_MODEL / 4 + 255) / 256, 256>>>(
        (const float4*)x, (uint4*)gXt);
    cvt_w_kernel<<<dim3((D_MODEL * D_MODEL / 4 + 255) / 256, 4), 256>>>(
        (const float4*)Wq, (const float4*)Wk, (const float4*)Wv, (const float4*)Wo,
        (uint4*)gWt);
    copy_past_k_kernel<<<(BHH * PAST * DHD / 4 + 255) / 256, 256>>>(
        (const float4*)pk, (float4*)kc, (uint4*)gKt);
    transpose_past_v_kernel<<<dim3(PAST / 32, DHD / 32, BHH), 256>>>(
        pv, vc, gVt);

    // 2) fused Q/K/V projections (16 warps/CTA, 3-stage)
    dim3 qkv_grid(D_MODEL / GBN, M_ROWS / GBM, 3);  // (16, 16, 3)
    gemm_pipe_kernel<1><<<qkv_grid, 512, GEMM_SMEM>>>(
        gXt, gWt, nullptr, kc, vc, gQt, gKt, gVt);

    // 3) causal attention
    flash_attn_tc_kernel<<<dim3(SS / FBM, BHH), 256, FA_SMEM>>>(gQt, gKt, gVt, gAt);

    // 4) output projection
    dim3 o_grid(D_MODEL / GBN, M_ROWS / GBM, 1);
    gemm_pipe_kernel<0><<<o_grid, 512, GEMM_SMEM>>>(
        gAt, gWt + 3 * (size_t)D_MODEL * D_MODEL, out, nullptr, nullptr,
        nullptr, nullptr, nullptr);
}

// round 10
// speedup vs baseline: 1.4052x; 1.1000x over previous
#include <cuda_runtime.h>
#include <cstdint>

#define D_MODEL 2048
#define BB 2
#define SS 2048
#define HH 16
#define DHD 128
#define PAST 2048
#define TOTAL 4096
#define BHH 32
#define M_ROWS 4096
// 1/sqrt(128) * log2(e): scores land in log2 domain -> softmax via EX2 only
#define QK_SCALE_L2E ((float)(0.08838834764831845 * 1.4426950408889634))

// Scratch (allocation-free rule: __device__ globals). All hold tf32 bit patterns.
__device__ uint32_t g_Xt[(size_t)M_ROWS * D_MODEL];
__device__ uint32_t g_Wt[4 * (size_t)D_MODEL * D_MODEL];
__device__ uint32_t g_Qt[(size_t)BHH * SS * DHD];        // (bh,s,dh), pre-scaled by QK_SCALE_L2E
__device__ uint32_t g_Kt[(size_t)BHH * TOTAL * DHD];     // (bh,key,dh)
__device__ uint32_t g_Vt[(size_t)BHH * DHD * TOTAL];     // V transposed (bh,dh,key)
__device__ uint32_t g_At[(size_t)BB * SS * D_MODEL];     // attn (b,s,dm)

// ---------------------------------------------------------------------------
// Helpers
// ---------------------------------------------------------------------------
__device__ __forceinline__ uint32_t to_tf32(float f) {
    uint32_t u;
    asm("cvt.rna.tf32.f32 %0, %1;" : "=r"(u) : "f"(f));
    return u;
}

__device__ __forceinline__ uint4 cvt4(float4 v) {
    uint4 r;
    r.x = to_tf32(v.x); r.y = to_tf32(v.y);
    r.z = to_tf32(v.z); r.w = to_tf32(v.w);
    return r;
}

__device__ __forceinline__ void mma_tf32(float* c,
                                         uint32_t a0, uint32_t a1, uint32_t a2, uint32_t a3,
                                         uint32_t b0, uint32_t b1) {
    asm volatile(
        "mma.sync.aligned.m16n8k8.row.col.f32.tf32.tf32.f32 "
        "{%0,%1,%2,%3}, {%4,%5,%6,%7}, {%8,%9}, {%0,%1,%2,%3};"
        : "+f"(c[0]), "+f"(c[1]), "+f"(c[2]), "+f"(c[3])
        : "r"(a0), "r"(a1), "r"(a2), "r"(a3), "r"(b0), "r"(b1));
}

// exp2 on MUFU: 1 issue slot. ex2(0) == 1.0f exactly.
__device__ __forceinline__ float ex2(float x) {
    float r;
    asm("ex2.approx.ftz.f32 %0, %1;" : "=f"(r) : "f"(x));
    return r;
}

__device__ __forceinline__ void cpasync16(void* smem_dst, const void* gsrc) {
    uint32_t s = (uint32_t)__cvta_generic_to_shared(smem_dst);
    asm volatile("cp.async.cg.shared.global [%0], [%1], 16;" :: "r"(s), "l"(gsrc));
}
__device__ __forceinline__ void cpasync_commit() {
    asm volatile("cp.async.commit_group;");
}
__device__ __forceinline__ void cpasync_wait0() {
    asm volatile("cp.async.wait_group 0;");
}
__device__ __forceinline__ void cpasync_wait1() {
    asm volatile("cp.async.wait_group 1;");
}

// ---------------------------------------------------------------------------
// Prep kernels
// ---------------------------------------------------------------------------
__global__ void cvt_x_kernel(const float4* __restrict__ x, uint4* __restrict__ out) {
    int i = blockIdx.x * blockDim.x + threadIdx.x;
    if (i < M_ROWS * D_MODEL / 4) out[i] = cvt4(x[i]);
}

__global__ void cvt_w_kernel(const float4* __restrict__ w0, const float4* __restrict__ w1,
                             const float4* __restrict__ w2, const float4* __restrict__ w3,
                             uint4* __restrict__ out) {
    int z = blockIdx.y;
    const float4* src = (z == 0) ? w0 : (z == 1) ? w1 : (z == 2) ? w2 : w3;
    int i = blockIdx.x * blockDim.x + threadIdx.x;
    const int n4 = D_MODEL * D_MODEL / 4;
    if (i < n4) out[(size_t)z * n4 + i] = cvt4(src[i]);
}

__global__ void copy_past_k_kernel(const float4* __restrict__ pk,
                                   float4* __restrict__ kc, uint4* __restrict__ kt) {
    int i = blockIdx.x * blockDim.x + threadIdx.x;
    if (i >= BHH * PAST * DHD / 4) return;
    int bh  = i >> 16;
    int rem = i & 65535;
    int dst = (bh << 17) + rem;
    float4 v = pk[i];
    kc[dst] = v;
    kt[dst] = cvt4(v);
}

__global__ __launch_bounds__(256) void transpose_past_v_kernel(
    const float* __restrict__ pv, float* __restrict__ vc, uint32_t* __restrict__ vt) {
    __shared__ float ts[32][33];
    int bh = blockIdx.z;
    int k0 = blockIdx.x * 32;
    int d0 = blockIdx.y * 32;
    int tx = threadIdx.x & 31, ty = threadIdx.x >> 5;

    const float* src = pv + ((size_t)bh * PAST + k0) * DHD + d0;
    float* cdst      = vc + ((size_t)bh * TOTAL + k0) * DHD + d0;
#pragma unroll
    for (int j = 0; j < 4; j++) {
        int r = ty + 8 * j;
        float v = src[(size_t)r * DHD + tx];
        cdst[(size_t)r * DHD + tx] = v;
        ts[r][tx] = v;
    }
    __syncthreads();
    uint32_t* tdst = vt + (size_t)bh * DHD * TOTAL;
#pragma unroll
    for (int j = 0; j < 4; j++) {
        int d = d0 + ty + 8 * j;
        tdst[(size_t)d * TOTAL + k0 + tx] = to_tf32(ts[tx][ty + 8 * j]);
    }
}

// ---------------------------------------------------------------------------
// TF32 GEMM: CTA 256x128, 512 threads, 16 warps (4m x 4n), warp tile 64x32,
// BK=32, 3-stage cp.async (ONE barrier/iter). tf32-bit inputs.
// FUSED=1: z selects Wq/Wk/Wv + Q/KV epilogues. FUSED=0: row-major fp32 C.
// ---------------------------------------------------------------------------
#define GBM 256
#define GBN 128
#define GLDW 48
#define GSTAGE ((GBM + GBN) * GLDW)
#define GEMM_SMEM (3 * GSTAGE * 4)   // 221184 B

template <int FUSED>
__global__ __launch_bounds__(512) void gemm_pipe_kernel(
    const uint32_t* __restrict__ A, const uint32_t* __restrict__ Wt,
    float* __restrict__ C0, float* __restrict__ C1, float* __restrict__ C2,
    uint32_t* __restrict__ Qt, uint32_t* __restrict__ Kt, uint32_t* __restrict__ Vt) {
    extern __shared__ uint32_t smg[];

    int t    = threadIdx.x;
    int warp = t >> 5, lane = t & 31;
    int gid  = lane >> 2, tid4 = lane & 3;
    int wm   = (warp & 3) * 64;
    int wn   = (warp >> 2) * 32;
    int m0   = blockIdx.y * GBM;
    int n0   = blockIdx.x * GBN;
    int z    = FUSED ? blockIdx.z : 0;

    const uint32_t* Ab = A + (size_t)m0 * D_MODEL;
    const uint32_t* Bb = Wt + (FUSED ? (size_t)z * D_MODEL * D_MODEL : 0) + (size_t)n0 * D_MODEL;

    float acc[4][4][4];
#pragma unroll
    for (int mf = 0; mf < 4; mf++)
#pragma unroll
        for (int nf = 0; nf < 4; nf++)
#pragma unroll
            for (int c = 0; c < 4; c++) acc[mf][nf][c] = 0.0f;

    const int NT = D_MODEL / 32;  // 64

#define GEMM_ISSUE(KT, STG)                                                        \
    {                                                                              \
        uint32_t* As_ = smg + (STG) * GSTAGE;                                      \
        uint32_t* Bs_ = As_ + GBM * GLDW;                                          \
        const uint32_t* ab = Ab + (KT) * 32;                                       \
        const uint32_t* bb = Bb + (KT) * 32;                                       \
        _Pragma("unroll")                                                          \
        for (int j = 0; j < 4; j++) {                                              \
            int g  = t + 512 * j;                                                  \
            int r  = g >> 3;                                                       \
            int c4 = g & 7;                                                        \
            cpasync16(As_ + r * GLDW + c4 * 4, ab + (size_t)r * D_MODEL + c4 * 4); \
        }                                                                          \
        _Pragma("unroll")                                                          \
        for (int j = 0; j < 2; j++) {                                              \
            int g  = t + 512 * j;                                                  \
            int r  = g >> 3;                                                       \
            int c4 = g & 7;                                                        \
            cpasync16(Bs_ + r * GLDW + c4 * 4, bb + (size_t)r * D_MODEL + c4 * 4); \
        }                                                                          \
    }

    GEMM_ISSUE(0, 0); cpasync_commit();
    GEMM_ISSUE(1, 1); cpasync_commit();

    for (int kt = 0; kt < NT; kt++) {
        cpasync_wait1();       // stage kt%3 complete
        __syncthreads();       // all warps done with stage (kt+2)%3 reads (iter kt-1)
        if (kt + 2 < NT) GEMM_ISSUE(kt + 2, (kt + 2) % 3);
        cpasync_commit();

        const uint32_t* As = smg + (kt % 3) * GSTAGE;
        const uint32_t* Bs = As + GBM * GLDW;
#pragma unroll
        for (int jj = 0; jj < 2; jj++) {
            uint4 bq[4];
#pragma unroll
            for (int nf = 0; nf < 4; nf++)
                bq[nf] = *(const uint4*)&Bs[(wn + 8 * nf + gid) * GLDW + jj * 16 + tid4 * 4];
#pragma unroll
            for (int mf = 0; mf < 4; mf++) {
                uint4 al = *(const uint4*)&As[(wm + 16 * mf + gid) * GLDW + jj * 16 + tid4 * 4];
                uint4 ah = *(const uint4*)&As[(wm + 16 * mf + gid + 8) * GLDW + jj * 16 + tid4 * 4];
#pragma unroll
                for (int nf = 0; nf < 4; nf++) {
                    mma_tf32(acc[mf][nf], al.x, ah.x, al.y, ah.y, bq[nf].x, bq[nf].y);
                    mma_tf32(acc[mf][nf], al.z, ah.z, al.w, ah.w, bq[nf].z, bq[nf].w);
                }
            }
        }
    }
#undef GEMM_ISSUE

    // Epilogue
#pragma unroll
    for (int mf = 0; mf < 4; mf++)
#pragma unroll
        for (int nf = 0; nf < 4; nf++)
#pragma unroll
            for (int h = 0; h < 2; h++) {
                int m = m0 + wm + 16 * mf + gid + 8 * h;
                int n = n0 + wn + 8 * nf + 2 * tid4;
                float2 v;
                v.x = acc[mf][nf][2 * h];
                v.y = acc[mf][nf][2 * h + 1];
                if (!FUSED) {
                    *(float2*)&C0[(size_t)m * D_MODEL + n] = v;
                } else {
                    int bb = m >> 11, ss = m & 2047;
                    int hd = n >> 7,  di = n & 127;
                    int bhh = bb * HH + hd;
                    if (z == 0) {
                        v.x *= QK_SCALE_L2E; v.y *= QK_SCALE_L2E;
                        uint2 u; u.x = to_tf32(v.x); u.y = to_tf32(v.y);
                        *(uint2*)&Qt[((size_t)bhh * SS + ss) * DHD + di] = u;
                    } else if (z == 1) {
                        size_t idx = ((size_t)bhh * TOTAL + (PAST + ss)) * DHD + di;
                        *(float2*)&C1[idx] = v;
                        uint2 u; u.x = to_tf32(v.x); u.y = to_tf32(v.y);
                        *(uint2*)&Kt[idx] = u;
                    } else {
                        size_t idx = ((size_t)bhh * TOTAL + (PAST + ss)) * DHD + di;
                        *(float2*)&C2[idx] = v;
                        size_t key = PAST + ss;
                        Vt[(size_t)bhh * DHD * TOTAL + (size_t)di * TOTAL + key]       = to_tf32(v.x);
                        Vt[(size_t)bhh * DHD * TOTAL + (size_t)(di + 1) * TOTAL + key] = to_tf32(v.y);
                    }
                }
            }
}

// ---------------------------------------------------------------------------
// Flash attention. tf32 mma, EX2-only softmax, REGISTER-resident P:
// PV uses mma k-slot permutation (slot t <-> key 2t, slot t+4 <-> key 2t+1)
// so the QK output fragment IS the PV A fragment -> no P smem at all.
// CTA: 64 q-rows, 128 threads, 4 warps (warp w: rows w*16..+15), 64 keys/iter.
// smem: Ks[2][64][144] + Vt[1][128][72] = 108 KB -> 2 CTAs/SM.
// ---------------------------------------------------------------------------
#define FBM 64
#define KLD 144
#define VTLD 72
#define FA_SMEM ((2 * 64 * KLD + 128 * VTLD) * 4)   // 110592 B

__global__ __launch_bounds__(128) void flash_attn_tc_kernel(
    const uint32_t* __restrict__ Qt, const uint32_t* __restrict__ Ktg,
    const uint32_t* __restrict__ Vtg, uint32_t* __restrict__ Out) {
    extern __shared__ uint32_t sm[];
    uint32_t* Ks  = sm;                      // [2][64][KLD]
    uint32_t* Vts = sm + 2 * 64 * KLD;       // [128][VTLD]

    int t    = threadIdx.x;
    int warp = t >> 5, lane = t & 31;
    int gid  = lane >> 2, tid4 = lane & 3;
    int mq   = warp * 16;

    int bh = blockIdx.y;
    int q0 = (gridDim.x - 1 - blockIdx.x) * FBM;  // big tiles launch first

    const uint32_t* Kb = Ktg + (size_t)bh * TOTAL * DHD;
    const uint32_t* Vb = Vtg + (size_t)bh * DHD * TOTAL;

    // Q fragments in registers: rows mq+gid, mq+gid+8; k = jj*16 + 4*tid4 .. +3
    uint4 q0r[8], q1r[8];
    {
        const uint32_t* Qrow0 = Qt + ((size_t)bh * SS + (q0 + mq + gid)) * DHD + 4 * tid4;
        const uint32_t* Qrow1 = Qrow0 + 8 * DHD;
#pragma unroll
        for (int jj = 0; jj < 8; jj++) {
            q0r[jj] = *(const uint4*)&Qrow0[jj * 16];
            q1r[jj] = *(const uint4*)&Qrow1[jj * 16];
        }
    }

    float m0r = -1e30f, m1r = -1e30f, l0 = 0.0f, l1 = 0.0f;
    float po[16][4];
#pragma unroll
    for (int nf = 0; nf < 16; nf++)
#pragma unroll
        for (int c = 0; c < 4; c++) po[nf][c] = 0.0f;

#define FA_ISSUE_K(KT, STG)                                                        \
    {                                                                              \
        int k0_ = (KT) * 64;                                                       \
        uint32_t* ksd = Ks + (STG) * 64 * KLD;                                     \
        _Pragma("unroll")                                                          \
        for (int i = 0; i < 16; i++) {                                             \
            int id = t + 128 * i;                                                  \
            int r = id >> 5, c = id & 31;                                          \
            cpasync16(ksd + r * KLD + c * 4, Kb + (size_t)(k0_ + r) * DHD + c * 4);\
        }                                                                          \
    }
#define FA_ISSUE_V(KT)                                                             \
    {                                                                              \
        int k0_ = (KT) * 64;                                                       \
        _Pragma("unroll")                                                          \
        for (int i = 0; i < 16; i++) {                                             \
            int id = t + 128 * i;                                                  \
            int d = id >> 4, kg = id & 15;                                         \
            cpasync16(Vts + d * VTLD + kg * 4, Vb + (size_t)d * TOTAL + k0_ + kg * 4); \
        }                                                                          \
    }

    int nkt = (PAST + q0 + FBM) / 64;
    FA_ISSUE_K(0, 0); cpasync_commit();

    for (int kt = 0; kt < nkt; kt++) {
        int k0 = kt * 64;
        bool masked = (k0 >= PAST + q0);
        int rel = k0 - PAST - q0;
        bool havenext = (kt + 1 < nkt);

        cpasync_wait0();   // K[kt] (and everything older) complete
        __syncthreads();   // K[kt] visible; V buffer free (prior PV done); kbuf-next free

        FA_ISSUE_V(kt); cpasync_commit();
        if (havenext) { FA_ISSUE_K(kt + 1, (kt + 1) & 1); cpasync_commit(); }

        const uint32_t* ksb = Ks + (kt & 1) * 64 * KLD;

        // S = Q K^T : 16 rows x 64 keys (log2-domain scores)
        float sc[8][4];
#pragma unroll
        for (int nf = 0; nf < 8; nf++)
#pragma unroll
            for (int c = 0; c < 4; c++) sc[nf][c] = 0.0f;

#pragma unroll
        for (int jj = 0; jj < 8; jj++) {
#pragma unroll
            for (int nf = 0; nf < 8; nf++) {
                uint4 b = *(const uint4*)&ksb[(nf * 8 + gid) * KLD + jj * 16 + 4 * tid4];
                mma_tf32(sc[nf], q0r[jj].x, q1r[jj].x, q0r[jj].y, q1r[jj].y, b.x, b.y);
                mma_tf32(sc[nf], q0r[jj].z, q1r[jj].z, q0r[jj].w, q1r[jj].w, b.z, b.w);
            }
        }

        if (masked) {
#pragma unroll
            for (int nf = 0; nf < 8; nf++)
#pragma unroll
                for (int c = 0; c < 4; c++) {
                    int col = nf * 8 + 2 * tid4 + (c & 1);
                    int row = mq + gid + 8 * (c >> 1);
                    if (col + rel > row) sc[nf][c] = -1e30f;
                }
        }

        // Warp-private online softmax (rows mq+gid, mq+gid+8), EX2 only
        float rm0 = -1e30f, rm1 = -1e30f;
#pragma unroll
        for (int nf = 0; nf < 8; nf++) {
            rm0 = fmaxf(rm0, fmaxf(sc[nf][0], sc[nf][1]));
            rm1 = fmaxf(rm1, fmaxf(sc[nf][2], sc[nf][3]));
        }
#pragma unroll
        for (int off = 1; off <= 2; off <<= 1) {
            rm0 = fmaxf(rm0, __shfl_xor_sync(0xffffffffu, rm0, off));
            rm1 = fmaxf(rm1, __shfl_xor_sync(0xffffffffu, rm1, off));
        }
        float mn0 = fmaxf(m0r, rm0);
        float mn1 = fmaxf(m1r, rm1);
        float alpha0 = ex2(m0r - mn0);
        float alpha1 = ex2(m1r - mn1);
        m0r = mn0; m1r = mn1;

        float rs0 = 0.0f, rs1 = 0.0f;
#pragma unroll
        for (int nf = 0; nf < 8; nf++) {
            float p0 = ex2(sc[nf][0] - mn0);
            float p1 = ex2(sc[nf][1] - mn0);
            float p2 = ex2(sc[nf][2] - mn1);
            float p3 = ex2(sc[nf][3] - mn1);
            rs0 += p0 + p1;
            rs1 += p2 + p3;
            // store tf32 bit patterns in place (P stays in registers)
            sc[nf][0] = __uint_as_float(to_tf32(p0));
            sc[nf][1] = __uint_as_float(to_tf32(p1));
            sc[nf][2] = __uint_as_float(to_tf32(p2));
            sc[nf][3] = __uint_as_float(to_tf32(p3));
        }
#pragma unroll
        for (int off = 1; off <= 2; off <<= 1) {
            rs0 += __shfl_xor_sync(0xffffffffu, rs0, off);
            rs1 += __shfl_xor_sync(0xffffffffu, rs1, off);
        }
        l0 = l0 * alpha0 + rs0;
        l1 = l1 * alpha1 + rs1;

        // Rescale O (skip when both alphas are exactly 1 across the warp)
        bool no_rescale = (alpha0 == 1.0f) & (alpha1 == 1.0f);
        if (!__all_sync(0xffffffffu, no_rescale)) {
#pragma unroll
            for (int nf = 0; nf < 16; nf++) {
                po[nf][0] *= alpha0; po[nf][1] *= alpha0;
                po[nf][2] *= alpha1; po[nf][3] *= alpha1;
            }
        }

        if (havenext) cpasync_wait1(); else cpasync_wait0();  // V[kt] done
        __syncthreads();                                      // V[kt] visible CTA-wide

        // O += P V : A = sc bits (k-slot t <-> key 2t, t+4 <-> 2t+1),
        //            B = Vt rows d, uint2 at keys {2t, 2t+1}
#pragma unroll
        for (int kk = 0; kk < 8; kk++) {
            uint32_t a0 = __float_as_uint(sc[kk][0]);
            uint32_t a1 = __float_as_uint(sc[kk][2]);
            uint32_t a2 = __float_as_uint(sc[kk][1]);
            uint32_t a3 = __float_as_uint(sc[kk][3]);
#pragma unroll
            for (int df = 0; df < 16; df++) {
                uint2 b = *(const uint2*)&Vts[(df * 8 + gid) * VTLD + kk * 8 + 2 * tid4];
                mma_tf32(po[df], a0, a1, a2, a3, b.x, b.y);
            }
        }
    }
#undef FA_ISSUE_K
#undef FA_ISSUE_V

    // Epilogue: normalize, convert to tf32 bits, write (b, s, d_model)
    float inv0 = 1.0f / l0;
    float inv1 = 1.0f / l1;
    int b  = bh >> 4;
    int hd = bh & 15;
    int row0 = q0 + mq + gid;
    int row1 = row0 + 8;
#pragma unroll
    for (int nf = 0; nf < 16; nf++) {
        int col = hd * DHD + nf * 8 + 2 * tid4;
        uint2 u0, u1;
        u0.x = to_tf32(po[nf][0] * inv0); u0.y = to_tf32(po[nf][1] * inv0);
        u1.x = to_tf32(po[nf][2] * inv1); u1.y = to_tf32(po[nf][3] * inv1);
        *(uint2*)&Out[(size_t)(b * SS + row0) * D_MODEL + col] = u0;
        *(uint2*)&Out[(size_t)(b * SS + row1) * D_MODEL + col] = u1;
    }
}

// ---------------------------------------------------------------------------
extern "C" void kernel_launch(void* const* d_in, const int* in_sizes, int n_in,
                              void* d_out, int out_size) {
    const float* x  = (const float*)d_in[0];
    const float* pk = (const float*)d_in[1];
    const float* pv = (const float*)d_in[2];
    const float* Wq = (const float*)d_in[3];
    const float* Wk = (const float*)d_in[4];
    const float* Wv = (const float*)d_in[5];
    const float* Wo = (const float*)d_in[6];

    float* out = (float*)d_out;
    float* kc  = out + (size_t)BB * SS * D_MODEL;
    float* vc  = kc + (size_t)BHH * TOTAL * DHD;

    uint32_t *gXt, *gWt, *gQt, *gKt, *gVt, *gAt;
    cudaGetSymbolAddress((void**)&gXt, g_Xt);
    cudaGetSymbolAddress((void**)&gWt, g_Wt);
    cudaGetSymbolAddress((void**)&gQt, g_Qt);
    cudaGetSymbolAddress((void**)&gKt, g_Kt);
    cudaGetSymbolAddress((void**)&gVt, g_Vt);
    cudaGetSymbolAddress((void**)&gAt, g_At);

    cudaFuncSetAttribute(gemm_pipe_kernel<1>, cudaFuncAttributeMaxDynamicSharedMemorySize, GEMM_SMEM);
    cudaFuncSetAttribute(gemm_pipe_kernel<0>, cudaFuncAttributeMaxDynamicSharedMemorySize, GEMM_SMEM);
    cudaFuncSetAttribute(flash_attn_tc_kernel, cudaFuncAttributeMaxDynamicSharedMemorySize, FA_SMEM);

    // 1) prep
    cvt_x_kernel<<<(M_ROWS * D_MODEL / 4 + 255) / 256, 256>>>(
        (const float4*)x, (uint4*)gXt);
    cvt_w_kernel<<<dim3((D_MODEL * D_MODEL / 4 + 255) / 256, 4), 256>>>(
        (const float4*)Wq, (const float4*)Wk, (const float4*)Wv, (const float4*)Wo,
        (uint4*)gWt);
    copy_past_k_kernel<<<(BHH * PAST * DHD / 4 + 255) / 256, 256>>>(
        (const float4*)pk, (float4*)kc, (uint4*)gKt);
    transpose_past_v_kernel<<<dim3(PAST / 32, DHD / 32, BHH), 256>>>(
        pv, vc, gVt);

    // 2) fused Q/K/V projections (16 warps/CTA, 3-stage)
    dim3 qkv_grid(D_MODEL / GBN, M_ROWS / GBM, 3);  // (16, 16, 3)
    gemm_pipe_kernel<1><<<qkv_grid, 512, GEMM_SMEM>>>(
        gXt, gWt, nullptr, kc, vc, gQt, gKt, gVt);

    // 3) causal attention (64-row CTAs, 2 CTAs/SM)
    flash_attn_tc_kernel<<<dim3(SS / FBM, BHH), 128, FA_SMEM>>>(gQt, gKt, gVt, gAt);

    // 4) output projection
    dim3 o_grid(D_MODEL / GBN, M_ROWS / GBM, 1);
    gemm_pipe_kernel<0><<<o_grid, 512, GEMM_SMEM>>>(
        gAt, gWt + 3 * (size_t)D_MODEL * D_MODEL, out, nullptr, nullptr,
        nullptr, nullptr, nullptr);
}

// round 11
// speedup vs baseline: 2.3229x; 1.6530x over previous
#include <cuda_runtime.h>
#include <cuda_fp16.h>
#include <cstdint>

#define D_MODEL 2048
#define BB 2
#define SS 2048
#define HH 16
#define DHD 128
#define PAST 2048
#define TOTAL 4096
#define BHH 32
#define M_ROWS 4096
// 1/sqrt(128) * log2(e): scores land in log2 domain -> softmax via EX2 only
#define QK_SCALE_L2E ((float)(0.08838834764831845 * 1.4426950408889634))

// Scratch (allocation-free rule). All hold packed fp16 (2 per uint32).
__device__ uint32_t g_Xh[(size_t)M_ROWS * D_MODEL / 2];
__device__ uint32_t g_Wh[4 * (size_t)D_MODEL * D_MODEL / 2];
__device__ uint32_t g_Qh[(size_t)BHH * SS * DHD / 2];    // PERMUTED fragment layout, pre-scaled
__device__ uint32_t g_Kh[(size_t)BHH * TOTAL * DHD / 2]; // plain (bh,key,dh)
__device__ uint32_t g_Vh[(size_t)BHH * DHD * TOTAL / 2]; // V transposed (bh,dh,key), plain
__device__ uint32_t g_Ah[(size_t)BB * SS * D_MODEL / 2]; // attn (b,s,dm), plain

// ---------------------------------------------------------------------------
// Helpers
// ---------------------------------------------------------------------------
__device__ __forceinline__ uint32_t pack_half2(float lo, float hi) {
    uint32_t r;
    asm("cvt.rn.f16x2.f32 %0, %1, %2;" : "=r"(r) : "f"(hi), "f"(lo));
    return r;
}

__device__ __forceinline__ void mma_f16(float* c,
                                        uint32_t a0, uint32_t a1, uint32_t a2, uint32_t a3,
                                        uint32_t b0, uint32_t b1) {
    asm volatile(
        "mma.sync.aligned.m16n8k16.row.col.f32.f16.f16.f32 "
        "{%0,%1,%2,%3}, {%4,%5,%6,%7}, {%8,%9}, {%0,%1,%2,%3};"
        : "+f"(c[0]), "+f"(c[1]), "+f"(c[2]), "+f"(c[3])
        : "r"(a0), "r"(a1), "r"(a2), "r"(a3), "r"(b0), "r"(b1));
}

__device__ __forceinline__ void ldsm4(uint32_t& r0, uint32_t& r1, uint32_t& r2, uint32_t& r3,
                                      uint32_t saddr) {
    asm volatile("ldmatrix.sync.aligned.m8n8.x4.shared.b16 {%0,%1,%2,%3}, [%4];"
                 : "=r"(r0), "=r"(r1), "=r"(r2), "=r"(r3) : "r"(saddr));
}
__device__ __forceinline__ void ldsm2(uint32_t& r0, uint32_t& r1, uint32_t saddr) {
    asm volatile("ldmatrix.sync.aligned.m8n8.x2.shared.b16 {%0,%1}, [%2];"
                 : "=r"(r0), "=r"(r1) : "r"(saddr));
}

// exp2 on MUFU: 1 issue slot. ex2(0) == 1.0f exactly.
__device__ __forceinline__ float ex2(float x) {
    float r;
    asm("ex2.approx.ftz.f32 %0, %1;" : "=f"(r) : "f"(x));
    return r;
}

__device__ __forceinline__ void cpasync16(void* smem_dst, const void* gsrc) {
    uint32_t s = (uint32_t)__cvta_generic_to_shared(smem_dst);
    asm volatile("cp.async.cg.shared.global [%0], [%1], 16;" :: "r"(s), "l"(gsrc));
}
__device__ __forceinline__ void cpasync_commit() {
    asm volatile("cp.async.commit_group;");
}
__device__ __forceinline__ void cpasync_wait0() {
    asm volatile("cp.async.wait_group 0;");
}
__device__ __forceinline__ void cpasync_wait1() {
    asm volatile("cp.async.wait_group 1;");
}

// ---------------------------------------------------------------------------
// Prep kernels
// ---------------------------------------------------------------------------
__global__ void cvt_x_kernel(const float4* __restrict__ x, uint2* __restrict__ out) {
    int i = blockIdx.x * blockDim.x + threadIdx.x;
    if (i < M_ROWS * D_MODEL / 4) {
        float4 v = x[i];
        out[i] = make_uint2(pack_half2(v.x, v.y), pack_half2(v.z, v.w));
    }
}

__global__ void cvt_w_kernel(const float4* __restrict__ w0, const float4* __restrict__ w1,
                             const float4* __restrict__ w2, const float4* __restrict__ w3,
                             uint2* __restrict__ out) {
    int z = blockIdx.y;
    const float4* src = (z == 0) ? w0 : (z == 1) ? w1 : (z == 2) ? w2 : w3;
    int i = blockIdx.x * blockDim.x + threadIdx.x;
    const int n4 = D_MODEL * D_MODEL / 4;
    if (i < n4) {
        float4 v = src[i];
        out[(size_t)z * n4 + i] = make_uint2(pack_half2(v.x, v.y), pack_half2(v.z, v.w));
    }
}

__global__ void copy_past_k_kernel(const float4* __restrict__ pk,
                                   float4* __restrict__ kc, uint2* __restrict__ kh) {
    int i = blockIdx.x * blockDim.x + threadIdx.x;
    if (i >= BHH * PAST * DHD / 4) return;
    int bh  = i >> 16;
    int rem = i & 65535;
    int dst = (bh << 17) + rem;
    float4 v = pk[i];
    kc[dst] = v;
    kh[dst] = make_uint2(pack_half2(v.x, v.y), pack_half2(v.z, v.w));
}

__global__ __launch_bounds__(256) void transpose_past_v_kernel(
    const float* __restrict__ pv, float* __restrict__ vc, uint32_t* __restrict__ vt) {
    __shared__ float ts[32][33];
    int bh = blockIdx.z;
    int k0 = blockIdx.x * 32;
    int d0 = blockIdx.y * 32;
    int tx = threadIdx.x & 31, ty = threadIdx.x >> 5;

    const float* src = pv + ((size_t)bh * PAST + k0) * DHD + d0;
    float* cdst      = vc + ((size_t)bh * TOTAL + k0) * DHD + d0;
#pragma unroll
    for (int j = 0; j < 4; j++) {
        int r = ty + 8 * j;
        float v = src[(size_t)r * DHD + tx];
        cdst[(size_t)r * DHD + tx] = v;
        ts[r][tx] = v;   // ts[key][d]
    }
    __syncthreads();
    uint32_t* td = vt + (size_t)bh * DHD * (TOTAL / 2);
    if (tx < 16) {
#pragma unroll
        for (int j = 0; j < 4; j++) {
            int dd = ty + 8 * j;
            td[(size_t)(d0 + dd) * (TOTAL / 2) + (k0 >> 1) + tx] =
                pack_half2(ts[2 * tx][dd], ts[2 * tx + 1][dd]);
        }
    }
}

// ---------------------------------------------------------------------------
// FP16 GEMM: CTA 256x128, 512 threads, 16 warps (4m x 4n), warp tile 64x32,
// BK=32 halfs (2 mma k-steps), 3-stage cp.async, ldmatrix fragments.
// FUSED=1: z selects Wq/Wk/Wv + Q(permuted fp16)/K(fp32+fp16)/V(fp32+fp16T).
// FUSED=0: row-major fp32 C (output projection).
// ---------------------------------------------------------------------------
#define GBM 256
#define GBN 128
#define LDWA 20                       // uint32 per smem row (16 data + 4 pad)
#define GSTG ((GBM + GBN) * LDWA)     // 7680 u32 per stage
#define GEMM_SMEM (3 * GSTG * 4)      // 92160 B

template <int FUSED>
__global__ __launch_bounds__(512) void gemm_f16_kernel(
    const uint32_t* __restrict__ A, const uint32_t* __restrict__ Wt,
    float* __restrict__ C0, float* __restrict__ C1, float* __restrict__ C2,
    uint32_t* __restrict__ Qh, uint32_t* __restrict__ Kh, uint32_t* __restrict__ Vh) {
    extern __shared__ uint32_t smg[];
    const int PITCH = D_MODEL / 2;   // 1024 u32 per global row

    int t    = threadIdx.x;
    int warp = t >> 5, lane = t & 31;
    int gid  = lane >> 2, tid4 = lane & 3;
    int wm   = (warp & 3) * 64;
    int wn   = (warp >> 2) * 32;
    int m0   = blockIdx.y * GBM;
    int n0   = blockIdx.x * GBN;
    int z    = FUSED ? blockIdx.z : 0;

    const uint32_t* Ab = A + (size_t)m0 * PITCH;
    const uint32_t* Bb = Wt + (FUSED ? (size_t)z * D_MODEL * PITCH : 0) + (size_t)n0 * PITCH;

    float acc[4][4][4];
#pragma unroll
    for (int mf = 0; mf < 4; mf++)
#pragma unroll
        for (int nf = 0; nf < 4; nf++)
#pragma unroll
            for (int c = 0; c < 4; c++) acc[mf][nf][c] = 0.0f;

    uint32_t smem_b = (uint32_t)__cvta_generic_to_shared(smg);
    // ldmatrix per-lane byte offsets (within stage)
    uint32_t aoff = ((wm + (lane & 15)) * LDWA + (lane >> 4) * 4) * 4;
    uint32_t boff = (GBM * LDWA + (wn + (lane & 7)) * LDWA + ((lane >> 3) & 1) * 4) * 4;

    const int NT = D_MODEL / 32;  // 64

#define GISSUE(KT, STG)                                                         \
    {                                                                           \
        uint32_t* As_ = smg + (STG) * GSTG;                                     \
        uint32_t* Bs_ = As_ + GBM * LDWA;                                       \
        const uint32_t* ab = Ab + (KT) * 16;                                    \
        const uint32_t* bb = Bb + (KT) * 16;                                    \
        _Pragma("unroll")                                                       \
        for (int j = 0; j < 2; j++) {                                           \
            int g = t + 512 * j;                                                \
            int r = g >> 2, c = g & 3;                                          \
            cpasync16(As_ + r * LDWA + c * 4, ab + (size_t)r * PITCH + c * 4);  \
        }                                                                       \
        {                                                                       \
            int r = t >> 2, c = t & 3;                                          \
            cpasync16(Bs_ + r * LDWA + c * 4, bb + (size_t)r * PITCH + c * 4);  \
        }                                                                       \
    }

    GISSUE(0, 0); cpasync_commit();
    GISSUE(1, 1); cpasync_commit();

    for (int kt = 0; kt < NT; kt++) {
        cpasync_wait1();
        __syncthreads();
        if (kt + 2 < NT) GISSUE(kt + 2, (kt + 2) % 3);
        cpasync_commit();

        uint32_t sb = smem_b + (kt % 3) * (GSTG * 4);
        uint32_t bf[4][4];
#pragma unroll
        for (int nf = 0; nf < 4; nf++) {
            ldsm2(bf[nf][0], bf[nf][1], sb + boff + nf * (8 * LDWA * 4));       // k 0..15
            ldsm2(bf[nf][2], bf[nf][3], sb + boff + nf * (8 * LDWA * 4) + 32);  // k 16..31
        }
#pragma unroll
        for (int mf = 0; mf < 4; mf++) {
            uint32_t x0, x1, x2, x3, y0, y1, y2, y3;
            ldsm4(x0, x1, x2, x3, sb + aoff + mf * (16 * LDWA * 4));        // k 0..15
            ldsm4(y0, y1, y2, y3, sb + aoff + mf * (16 * LDWA * 4) + 32);   // k 16..31
#pragma unroll
            for (int nf = 0; nf < 4; nf++) {
                mma_f16(acc[mf][nf], x0, x1, x2, x3, bf[nf][0], bf[nf][1]);
                mma_f16(acc[mf][nf], y0, y1, y2, y3, bf[nf][2], bf[nf][3]);
            }
        }
    }
#undef GISSUE

    // Epilogue
#pragma unroll
    for (int mf = 0; mf < 4; mf++)
#pragma unroll
        for (int nf = 0; nf < 4; nf++)
#pragma unroll
            for (int h = 0; h < 2; h++) {
                int m = m0 + wm + 16 * mf + gid + 8 * h;
                int n = n0 + wn + 8 * nf + 2 * tid4;
                float vx = acc[mf][nf][2 * h];
                float vy = acc[mf][nf][2 * h + 1];
                if (!FUSED) {
                    *(float2*)&C0[(size_t)m * D_MODEL + n] = make_float2(vx, vy);
                } else {
                    int bb = m >> 11, ss = m & 2047;
                    int hd = n >> 7,  di = n & 127;
                    int bhh = bb * HH + hd;
                    if (z == 0) {
                        vx *= QK_SCALE_L2E; vy *= QK_SCALE_L2E;
                        // permuted fragment layout: pos = blk*16 + 4*tid4 + nf
                        Qh[((size_t)bhh * SS + ss) * 64 + ((di >> 5) << 4) + 4 * tid4 + nf] =
                            pack_half2(vx, vy);
                    } else if (z == 1) {
                        size_t rowk = (size_t)bhh * TOTAL + (PAST + ss);
                        *(float2*)&C1[rowk * DHD + di] = make_float2(vx, vy);
                        Kh[rowk * 64 + (di >> 1)] = pack_half2(vx, vy);
                    } else {
                        size_t rowk = (size_t)bhh * TOTAL + (PAST + ss);
                        *(float2*)&C2[rowk * DHD + di] = make_float2(vx, vy);
                        __half* vh = (__half*)Vh;
                        size_t base = (size_t)bhh * DHD * TOTAL + (size_t)(PAST + ss);
                        vh[base + (size_t)di * TOTAL]       = __float2half(vx);
                        vh[base + (size_t)(di + 1) * TOTAL] = __float2half(vy);
                    }
                }
            }
}

// ---------------------------------------------------------------------------
// Flash attention, fp16 m16n8k16 mma. Q fragments from permuted global; K
// double-buffered cp.async + ldmatrix; Vt single-buffered; P stays in regs
// (QK output fragment IS the PV A fragment after half2 packing).
// CTA: 64 q-rows, 128 threads, 4 warps (warp w: rows w*16..+15), 64 keys/iter.
// smem: Ks[2][64][68] + Vt[128][36] u32 = 53248 B.
// ---------------------------------------------------------------------------
#define FBM 64
#define KLD2 68
#define VLD2 36
#define FA_SMEM ((2 * 64 * KLD2 + 128 * VLD2) * 4)   // 53248 B

__global__ __launch_bounds__(128) void flash_attn_f16_kernel(
    const uint32_t* __restrict__ Qh, const uint32_t* __restrict__ Khg,
    const uint32_t* __restrict__ Vhg, uint32_t* __restrict__ Out) {
    extern __shared__ uint32_t sm[];
    uint32_t* Ks  = sm;                   // [2][64][KLD2]
    uint32_t* Vts = sm + 2 * 64 * KLD2;   // [128][VLD2]

    int t    = threadIdx.x;
    int warp = t >> 5, lane = t & 31;
    int gid  = lane >> 2, tid4 = lane & 3;
    int mq   = warp * 16;

    int bh = blockIdx.y;
    int q0 = (gridDim.x - 1 - blockIdx.x) * FBM;  // big tiles launch first

    const uint32_t* Kb = Khg + (size_t)bh * TOTAL * 64;
    const uint32_t* Vb = Vhg + (size_t)bh * DHD * (TOTAL / 2);

    // Q fragments from permuted global: uint4 blk gives (a0,a2) for steps 2blk, 2blk+1
    uint4 qA[4], qB[4];
    {
        const uint32_t* Qr0 = Qh + ((size_t)bh * SS + (q0 + mq + gid)) * 64 + 4 * tid4;
        const uint32_t* Qr1 = Qr0 + 8 * 64;
#pragma unroll
        for (int blk = 0; blk < 4; blk++) {
            qA[blk] = *(const uint4*)&Qr0[blk * 16];
            qB[blk] = *(const uint4*)&Qr1[blk * 16];
        }
    }

    uint32_t smem_b = (uint32_t)__cvta_generic_to_shared(sm);
    uint32_t koff = ((lane & 7) * KLD2 + (lane >> 3) * 4) * 4;
    uint32_t voff = (2 * 64 * KLD2) * 4 + ((lane & 7) * VLD2 + (lane >> 3) * 4) * 4;

    float m0r = -1e30f, m1r = -1e30f, l0 = 0.0f, l1 = 0.0f;
    float po[16][4];
#pragma unroll
    for (int df = 0; df < 16; df++)
#pragma unroll
        for (int c = 0; c < 4; c++) po[df][c] = 0.0f;

#define FA_ISSUE_K(KT, STG)                                                        \
    {                                                                              \
        int k0_ = (KT) * 64;                                                       \
        uint32_t* ksd = Ks + (STG) * 64 * KLD2;                                    \
        _Pragma("unroll")                                                          \
        for (int i = 0; i < 8; i++) {                                              \
            int id = t + 128 * i;                                                  \
            int r = id >> 4, c = id & 15;                                          \
            cpasync16(ksd + r * KLD2 + c * 4, Kb + (size_t)(k0_ + r) * 64 + c * 4);\
        }                                                                          \
    }
#define FA_ISSUE_V(KT)                                                             \
    {                                                                              \
        int k0_ = (KT) * 64;                                                       \
        _Pragma("unroll")                                                          \
        for (int i = 0; i < 8; i++) {                                              \
            int id = t + 128 * i;                                                  \
            int r = id >> 3, c = id & 7;                                           \
            cpasync16(Vts + r * VLD2 + c * 4,                                      \
                      Vb + (size_t)r * (TOTAL / 2) + (k0_ >> 1) + c * 4);          \
        }                                                                          \
    }

    int nkt = (PAST + q0 + FBM) / 64;
    FA_ISSUE_K(0, 0); cpasync_commit();

    for (int kt = 0; kt < nkt; kt++) {
        int k0 = kt * 64;
        bool masked = (k0 >= PAST + q0);
        int rel = k0 - PAST - q0;
        bool havenext = (kt + 1 < nkt);

        cpasync_wait0();   // K[kt] complete
        __syncthreads();   // K visible; V buffer free (prior PV done); next K-buf free

        FA_ISSUE_V(kt); cpasync_commit();
        if (havenext) { FA_ISSUE_K(kt + 1, (kt + 1) & 1); cpasync_commit(); }

        uint32_t kstage = smem_b + (kt & 1) * (64 * KLD2 * 4);

        // S = Q K^T : 16 rows x 64 keys (log2-domain scores)
        float sc[8][4];
#pragma unroll
        for (int nf = 0; nf < 8; nf++)
#pragma unroll
            for (int c = 0; c < 4; c++) sc[nf][c] = 0.0f;

#pragma unroll
        for (int q = 0; q < 4; q++) {   // k16 steps 2q, 2q+1
#pragma unroll
            for (int nf = 0; nf < 8; nf++) {
                uint32_t b0, b1, b2, b3;
                ldsm4(b0, b1, b2, b3, kstage + koff + nf * (8 * KLD2 * 4) + q * 64);
                mma_f16(sc[nf], qA[q].x, qB[q].x, qA[q].y, qB[q].y, b0, b1);
                mma_f16(sc[nf], qA[q].z, qB[q].z, qA[q].w, qB[q].w, b2, b3);
            }
        }

        if (masked) {
#pragma unroll
            for (int nf = 0; nf < 8; nf++)
#pragma unroll
                for (int c = 0; c < 4; c++) {
                    int col = nf * 8 + 2 * tid4 + (c & 1);
                    int row = mq + gid + 8 * (c >> 1);
                    if (col + rel > row) sc[nf][c] = -1e30f;
                }
        }

        // Warp-private online softmax (rows mq+gid, mq+gid+8), EX2 only
        float rm0 = -1e30f, rm1 = -1e30f;
#pragma unroll
        for (int nf = 0; nf < 8; nf++) {
            rm0 = fmaxf(rm0, fmaxf(sc[nf][0], sc[nf][1]));
            rm1 = fmaxf(rm1, fmaxf(sc[nf][2], sc[nf][3]));
        }
#pragma unroll
        for (int off = 1; off <= 2; off <<= 1) {
            rm0 = fmaxf(rm0, __shfl_xor_sync(0xffffffffu, rm0, off));
            rm1 = fmaxf(rm1, __shfl_xor_sync(0xffffffffu, rm1, off));
        }
        float mn0 = fmaxf(m0r, rm0);
        float mn1 = fmaxf(m1r, rm1);
        float alpha0 = ex2(m0r - mn0);
        float alpha1 = ex2(m1r - mn1);
        m0r = mn0; m1r = mn1;

        float rs0 = 0.0f, rs1 = 0.0f;
#pragma unroll
        for (int nf = 0; nf < 8; nf++) {
            float p0 = ex2(sc[nf][0] - mn0);
            float p1 = ex2(sc[nf][1] - mn0);
            float p2 = ex2(sc[nf][2] - mn1);
            float p3 = ex2(sc[nf][3] - mn1);
            rs0 += p0 + p1;
            rs1 += p2 + p3;
            sc[nf][0] = p0; sc[nf][1] = p1; sc[nf][2] = p2; sc[nf][3] = p3;
        }
#pragma unroll
        for (int off = 1; off <= 2; off <<= 1) {
            rs0 += __shfl_xor_sync(0xffffffffu, rs0, off);
            rs1 += __shfl_xor_sync(0xffffffffu, rs1, off);
        }
        l0 = l0 * alpha0 + rs0;
        l1 = l1 * alpha1 + rs1;

        bool no_rescale = (alpha0 == 1.0f) & (alpha1 == 1.0f);
        if (!__all_sync(0xffffffffu, no_rescale)) {
#pragma unroll
            for (int df = 0; df < 16; df++) {
                po[df][0] *= alpha0; po[df][1] *= alpha0;
                po[df][2] *= alpha1; po[df][3] *= alpha1;
            }
        }

        if (havenext) cpasync_wait1(); else cpasync_wait0();  // V[kt] done
        __syncthreads();                                      // V visible CTA-wide

        // O += P V : A from QK output regs (packed half2), B via ldmatrix on Vt
#pragma unroll
        for (int q = 0; q < 2; q++) {   // key k16-steps 2q, 2q+1 (keys 32q..32q+31)
            uint32_t pa[8];
            pa[0] = pack_half2(sc[4 * q + 0][0], sc[4 * q + 0][1]);
            pa[1] = pack_half2(sc[4 * q + 0][2], sc[4 * q + 0][3]);
            pa[2] = pack_half2(sc[4 * q + 1][0], sc[4 * q + 1][1]);
            pa[3] = pack_half2(sc[4 * q + 1][2], sc[4 * q + 1][3]);
            pa[4] = pack_half2(sc[4 * q + 2][0], sc[4 * q + 2][1]);
            pa[5] = pack_half2(sc[4 * q + 2][2], sc[4 * q + 2][3]);
            pa[6] = pack_half2(sc[4 * q + 3][0], sc[4 * q + 3][1]);
            pa[7] = pack_half2(sc[4 * q + 3][2], sc[4 * q + 3][3]);
#pragma unroll
            for (int df = 0; df < 16; df++) {
                uint32_t b0, b1, b2, b3;
                ldsm4(b0, b1, b2, b3, smem_b + voff + df * (8 * VLD2 * 4) + q * 64);
                mma_f16(po[df], pa[0], pa[1], pa[2], pa[3], b0, b1);
                mma_f16(po[df], pa[4], pa[5], pa[6], pa[7], b2, b3);
            }
        }
    }
#undef FA_ISSUE_K
#undef FA_ISSUE_V

    // Epilogue: normalize, pack fp16, write (b, s, d_model)
    float inv0 = 1.0f / l0;
    float inv1 = 1.0f / l1;
    int b  = bh >> 4;
    int hd = bh & 15;
    int row0 = q0 + mq + gid;
    int row1 = row0 + 8;
#pragma unroll
    for (int df = 0; df < 16; df++) {
        int cu = hd * 64 + 4 * df + tid4;
        Out[(size_t)(b * SS + row0) * (D_MODEL / 2) + cu] =
            pack_half2(po[df][0] * inv0, po[df][1] * inv0);
        Out[(size_t)(b * SS + row1) * (D_MODEL / 2) + cu] =
            pack_half2(po[df][2] * inv1, po[df][3] * inv1);
    }
}

// ---------------------------------------------------------------------------
extern "C" void kernel_launch(void* const* d_in, const int* in_sizes, int n_in,
                              void* d_out, int out_size) {
    const float* x  = (const float*)d_in[0];
    const float* pk = (const float*)d_in[1];
    const float* pv = (const float*)d_in[2];
    const float* Wq = (const float*)d_in[3];
    const float* Wk = (const float*)d_in[4];
    const float* Wv = (const float*)d_in[5];
    const float* Wo = (const float*)d_in[6];

    float* out = (float*)d_out;
    float* kc  = out + (size_t)BB * SS * D_MODEL;
    float* vc  = kc + (size_t)BHH * TOTAL * DHD;

    uint32_t *gXh, *gWh, *gQh, *gKh, *gVh, *gAh;
    cudaGetSymbolAddress((void**)&gXh, g_Xh);
    cudaGetSymbolAddress((void**)&gWh, g_Wh);
    cudaGetSymbolAddress((void**)&gQh, g_Qh);
    cudaGetSymbolAddress((void**)&gKh, g_Kh);
    cudaGetSymbolAddress((void**)&gVh, g_Vh);
    cudaGetSymbolAddress((void**)&gAh, g_Ah);

    cudaFuncSetAttribute(gemm_f16_kernel<1>, cudaFuncAttributeMaxDynamicSharedMemorySize, GEMM_SMEM);
    cudaFuncSetAttribute(gemm_f16_kernel<0>, cudaFuncAttributeMaxDynamicSharedMemorySize, GEMM_SMEM);
    cudaFuncSetAttribute(flash_attn_f16_kernel, cudaFuncAttributeMaxDynamicSharedMemorySize, FA_SMEM);

    // 1) prep
    cvt_x_kernel<<<(M_ROWS * D_MODEL / 4 + 255) / 256, 256>>>(
        (const float4*)x, (uint2*)gXh);
    cvt_w_kernel<<<dim3((D_MODEL * D_MODEL / 4 + 255) / 256, 4), 256>>>(
        (const float4*)Wq, (const float4*)Wk, (const float4*)Wv, (const float4*)Wo,
        (uint2*)gWh);
    copy_past_k_kernel<<<(BHH * PAST * DHD / 4 + 255) / 256, 256>>>(
        (const float4*)pk, (float4*)kc, (uint2*)gKh);
    transpose_past_v_kernel<<<dim3(PAST / 32, DHD / 32, BHH), 256>>>(
        pv, vc, gVh);

    // 2) fused Q/K/V projections (fp16 tensor cores)
    dim3 qkv_grid(D_MODEL / GBN, M_ROWS / GBM, 3);  // (16, 16, 3)
    gemm_f16_kernel<1><<<qkv_grid, 512, GEMM_SMEM>>>(
        gXh, gWh, nullptr, kc, vc, gQh, gKh, gVh);

    // 3) causal attention
    flash_attn_f16_kernel<<<dim3(SS / FBM, BHH), 128, FA_SMEM>>>(gQh, gKh, gVh, gAh);

    // 4) output projection (Wo = slot 3 of gWh)
    dim3 o_grid(D_MODEL / GBN, M_ROWS / GBM, 1);
    gemm_f16_kernel<0><<<o_grid, 512, GEMM_SMEM>>>(
        gAh, gWh + 3 * (size_t)D_MODEL * D_MODEL / 2, out, nullptr, nullptr,
        nullptr, nullptr, nullptr);
}